// round 9
// baseline (speedup 1.0000x reference)
#include <cuda_runtime.h>
#include <cuda_bf16.h>
#include <cstdint>

#define T_SEQ 2048
#define E_DIM 1024
#define H_NUM 16
#define L_DIM 64
#define NMID  1152   // 1024 q_lat cols + 64 latent_k + 64 latent_v

// ==================== helpers ====================
__device__ __forceinline__ uint32_t f2tf32(float x) {
    uint32_t b;
    asm("cvt.rna.tf32.f32 %0, %1;" : "=r"(b) : "f"(x));
    return b;
}

// tf32: D(16x8) += A(16x8) * B(8x8)
__device__ __forceinline__ void mma_tf32(float* c, const uint32_t* a, uint32_t b0, uint32_t b1) {
    asm volatile(
        "mma.sync.aligned.m16n8k8.row.col.f32.tf32.tf32.f32 "
        "{%0,%1,%2,%3}, {%4,%5,%6,%7}, {%8,%9}, {%0,%1,%2,%3};"
        : "+f"(c[0]), "+f"(c[1]), "+f"(c[2]), "+f"(c[3])
        : "r"(a[0]), "r"(a[1]), "r"(a[2]), "r"(a[3]), "r"(b0), "r"(b1));
}

// bf16: D(16x8) += A(16x16) * B(16x8)
__device__ __forceinline__ void mma_bf16(float* c, const uint32_t* a, uint32_t b0, uint32_t b1) {
    asm volatile(
        "mma.sync.aligned.m16n8k16.row.col.f32.bf16.bf16.f32 "
        "{%0,%1,%2,%3}, {%4,%5,%6,%7}, {%8,%9}, {%0,%1,%2,%3};"
        : "+f"(c[0]), "+f"(c[1]), "+f"(c[2]), "+f"(c[3])
        : "r"(a[0]), "r"(a[1]), "r"(a[2]), "r"(a[3]), "r"(b0), "r"(b1));
}

__device__ __forceinline__ void ldsm_x4(uint32_t& r0, uint32_t& r1, uint32_t& r2, uint32_t& r3,
                                        uint32_t addr) {
    asm volatile("ldmatrix.sync.aligned.m8n8.x4.shared.b16 {%0,%1,%2,%3}, [%4];"
                 : "=r"(r0), "=r"(r1), "=r"(r2), "=r"(r3) : "r"(addr));
}

__device__ __forceinline__ void ldsm_x4_t(uint32_t& r0, uint32_t& r1, uint32_t& r2, uint32_t& r3,
                                          uint32_t addr) {
    asm volatile("ldmatrix.sync.aligned.m8n8.x4.trans.shared.b16 {%0,%1,%2,%3}, [%4];"
                 : "=r"(r0), "=r"(r1), "=r"(r2), "=r"(r3) : "r"(addr));
}

__device__ __forceinline__ uint32_t smem_u32(const void* p) {
    uint32_t a;
    asm("{ .reg .u64 t; cvta.to.shared.u64 t, %1; cvt.u32.u64 %0, t; }" : "=r"(a) : "l"(p));
    return a;
}

__device__ __forceinline__ void cp_async16(uint32_t dst, const void* src) {
    asm volatile("cp.async.cg.shared.global [%0], [%1], 16;" :: "r"(dst), "l"(src));
}
#define CP_COMMIT()  asm volatile("cp.async.commit_group;" ::: "memory")
#define CP_WAIT(N)   asm volatile("cp.async.wait_group %0;" :: "n"(N) : "memory")

__device__ __forceinline__ void bsplit(float x, __nv_bfloat16& h, __nv_bfloat16& l) {
    h = __float2bfloat16_rn(x);
    l = __float2bfloat16_rn(x - __bfloat162float(h));
}

// pack two floats (lo = even-k, hi = odd-k) into bf16x2 register
__device__ __forceinline__ uint32_t packbf(float lo, float hi) {
    __nv_bfloat162 t = __floats2bfloat162_rn(lo, hi);
    return *(uint32_t*)&t;
}

// ==================== device scratch ====================
__device__ __nv_bfloat16 g_W1Th[NMID * E_DIM], g_W1Tl[NMID * E_DIM];
__device__ __nv_bfloat16 g_W2Th[E_DIM * E_DIM], g_W2Tl[E_DIM * E_DIM];
__device__ __nv_bfloat16 g_Ah[T_SEQ * E_DIM],  g_Al[T_SEQ * E_DIM];
__device__ float g_mid[T_SEQ * NMID];               // [q_lat*0.125 | latent_k] tf32-rounded
__device__ __nv_bfloat16 g_Vh[T_SEQ * 64], g_Vl[T_SEQ * 64];  // latent_v bf16 hi/lo
__device__ float g_ctx[T_SEQ * E_DIM];              // ctx_lat [t, h*64+l]

// ---------------- split A: bf16 hi/lo decomposition ----------------
__global__ __launch_bounds__(256) void split_kernel(const float* __restrict__ src,
                                                    __nv_bfloat16* __restrict__ hi,
                                                    __nv_bfloat16* __restrict__ lo) {
    int i = (blockIdx.x * 256 + threadIdx.x) * 4;
    float4 v = *(const float4*)&src[i];
    __nv_bfloat16 h[4], l[4];
    bsplit(v.x, h[0], l[0]); bsplit(v.y, h[1], l[1]);
    bsplit(v.z, h[2], l[2]); bsplit(v.w, h[3], l[3]);
    *(__nv_bfloat162*)&hi[i]     = __nv_bfloat162{h[0], h[1]};
    *(__nv_bfloat162*)&hi[i + 2] = __nv_bfloat162{h[2], h[3]};
    *(__nv_bfloat162*)&lo[i]     = __nv_bfloat162{l[0], l[1]};
    *(__nv_bfloat162*)&lo[i + 2] = __nv_bfloat162{l[2], l[3]};
}

// ---------------- prep 1: W1T[h*64+l][e] = sum_d Wq[h*64+d, e] * q2l[h,d,l] ----
__global__ __launch_bounds__(256) void prep_w1_kernel(const float* __restrict__ Wq,
                                                      const float* __restrict__ q2l) {
    __shared__ float Wqs[64][65];
    __shared__ float Qls[64][65];
    const int h  = blockIdx.y;
    const int e0 = blockIdx.x * 64;
    const int tid = threadIdx.x, tx = tid & 15, ty = tid >> 4;

    #pragma unroll
    for (int i = 0; i < 16; i++) {
        int lin = tid + i * 256;
        int c = lin & 63, r = lin >> 6;
        Wqs[r][c] = Wq[(h * 64 + r) * E_DIM + e0 + c];
        Qls[r][c] = q2l[(h * 64 + r) * 64 + c];
    }
    __syncthreads();

    float acc[4][4];
    #pragma unroll
    for (int i = 0; i < 4; i++)
        #pragma unroll
        for (int j = 0; j < 4; j++) acc[i][j] = 0.f;

    #pragma unroll 8
    for (int d = 0; d < 64; d++) {
        float a[4], b[4];
        #pragma unroll
        for (int i = 0; i < 4; i++) a[i] = Wqs[d][ty * 4 + i];
        #pragma unroll
        for (int j = 0; j < 4; j++) b[j] = Qls[d][tx * 4 + j];
        #pragma unroll
        for (int i = 0; i < 4; i++)
            #pragma unroll
            for (int j = 0; j < 4; j++) acc[i][j] += a[i] * b[j];
    }
    #pragma unroll
    for (int j = 0; j < 4; j++)
        #pragma unroll
        for (int i = 0; i < 4; i++) {
            int idx = (h * 64 + tx * 4 + j) * E_DIM + e0 + ty * 4 + i;
            __nv_bfloat16 hf, lf; bsplit(acc[i][j], hf, lf);
            g_W1Th[idx] = hf; g_W1Tl[idx] = lf;
        }
}

// ---------------- prep 2: W1T rows 1024+l / 1088+l are Wk_down / Wv_down ----
__global__ __launch_bounds__(256) void prep_kv_kernel(const float* __restrict__ Wk,
                                                      const float* __restrict__ Wv) {
    int idx = blockIdx.x * 256 + threadIdx.x;   // 64 * 1024
    __nv_bfloat16 hf, lf;
    bsplit(Wk[idx], hf, lf);
    g_W1Th[1024 * E_DIM + idx] = hf; g_W1Tl[1024 * E_DIM + idx] = lf;
    bsplit(Wv[idx], hf, lf);
    g_W1Th[1088 * E_DIM + idx] = hf; g_W1Tl[1088 * E_DIM + idx] = lf;
}

// ---------------- prep 3: W2T[e][h*64+l] = sum_d v_up[h,l,d] * Wout[e, h*64+d] ----
__global__ __launch_bounds__(256) void prep_w2_kernel(const float* __restrict__ vup,
                                                      const float* __restrict__ Wout) {
    __shared__ __align__(16) float Wos[64][68];
    __shared__ __align__(16) float Vus[64][68];
    const int h  = blockIdx.y;
    const int e0 = blockIdx.x * 64;
    const int tid = threadIdx.x, tx = tid & 15, ty = tid >> 4;

    #pragma unroll
    for (int i = 0; i < 16; i++) {
        int lin = tid + i * 256;
        int c = lin & 63, r = lin >> 6;
        Wos[r][c] = Wout[(e0 + r) * E_DIM + h * 64 + c];
        Vus[r][c] = vup[(h * 64 + r) * 64 + c];
    }
    __syncthreads();

    float acc[4][4];
    #pragma unroll
    for (int i = 0; i < 4; i++)
        #pragma unroll
        for (int j = 0; j < 4; j++) acc[i][j] = 0.f;

    #pragma unroll
    for (int d4 = 0; d4 < 16; d4++) {
        float4 a[4], b[4];
        #pragma unroll
        for (int i = 0; i < 4; i++) a[i] = *(const float4*)&Vus[ty * 4 + i][d4 * 4];
        #pragma unroll
        for (int j = 0; j < 4; j++) b[j] = *(const float4*)&Wos[tx * 4 + j][d4 * 4];
        #pragma unroll
        for (int i = 0; i < 4; i++)
            #pragma unroll
            for (int j = 0; j < 4; j++)
                acc[i][j] += a[i].x * b[j].x + a[i].y * b[j].y +
                             a[i].z * b[j].z + a[i].w * b[j].w;
    }
    #pragma unroll
    for (int j = 0; j < 4; j++)
        #pragma unroll
        for (int i = 0; i < 4; i++) {
            int idx = (e0 + tx * 4 + j) * E_DIM + h * 64 + ty * 4 + i;
            __nv_bfloat16 hf, lf; bsplit(acc[i][j], hf, lf);
            g_W2Th[idx] = hf; g_W2Tl[idx] = lf;
        }
}

// ==================== bf16 3-term mma.sync GEMM ====================
#define ROWB 80
#define SA_H 0
#define SA_L (128 * ROWB)
#define SB_H (2 * 128 * ROWB)
#define SB_L (SB_H + 64 * ROWB)
#define SSZ  (SB_L + 64 * ROWB)
#define GEMM_SMEM (2 * SSZ)

__global__ __launch_bounds__(256, 2) void gemm_bf3(const __nv_bfloat16* __restrict__ Ah,
                                                   const __nv_bfloat16* __restrict__ Al,
                                                   const __nv_bfloat16* __restrict__ Bh,
                                                   const __nv_bfloat16* __restrict__ Bl,
                                                   float* __restrict__ C,
                                                   int N, int K, int mode) {
    extern __shared__ char gsm[];
    const uint32_t sbase = smem_u32(gsm);

    const int tid = threadIdx.x;
    const int wid = tid >> 5, lane = tid & 31;
    const int g = lane >> 2, tig = lane & 3;
    const int wm = wid & 3, wn = wid >> 2;
    const int m0 = blockIdx.y * 128;
    const int n0 = blockIdx.x * 64;
    const int nst = K >> 5;

    const uint32_t aRow = lane & 15;
    const uint32_t aSel = ((lane >> 4) & 1) * 16;
    const uint32_t bRow = (lane & 7) + ((lane & 16) ? 8 : 0);
    const uint32_t bSel = (lane & 8) ? 16 : 0;

    float c[2][4][4];
    #pragma unroll
    for (int mt = 0; mt < 2; mt++)
        #pragma unroll
        for (int nt = 0; nt < 4; nt++)
            #pragma unroll
            for (int j = 0; j < 4; j++) c[mt][nt][j] = 0.f;

    auto fetch = [&](int k0, int b) {
        const uint32_t s0 = sbase + (uint32_t)(b * SSZ);
        #pragma unroll
        for (int i = 0; i < 6; i++) {
            int idx = tid + i * 256;
            if (idx < 1024) {
                int t = idx >> 9;
                int r = (idx & 511) >> 2, cc = idx & 3;
                const __nv_bfloat16* src = (t ? Al : Ah) + (size_t)(m0 + r) * K + k0 + cc * 8;
                cp_async16(s0 + (t ? SA_L : SA_H) + r * ROWB + cc * 16, src);
            } else {
                int t = (idx - 1024) >> 8;
                int r = ((idx - 1024) & 255) >> 2, cc = idx & 3;
                const __nv_bfloat16* src = (t ? Bl : Bh) + (size_t)(n0 + r) * K + k0 + cc * 8;
                cp_async16(s0 + (t ? SB_L : SB_H) + r * ROWB + cc * 16, src);
            }
        }
        CP_COMMIT();
    };

    fetch(0, 0);

    for (int s = 0; s < nst; s++) {
        const int buf = s & 1;
        if (s + 1 < nst) { fetch((s + 1) << 5, buf ^ 1); CP_WAIT(1); }
        else             { CP_WAIT(0); }
        __syncthreads();

        const uint32_t sb = sbase + (uint32_t)(buf * SSZ);
        #pragma unroll
        for (int ks = 0; ks < 2; ks++) {
            uint32_t ah[2][4], al[2][4];
            #pragma unroll
            for (int mt = 0; mt < 2; mt++) {
                uint32_t ra = (wm * 32 + mt * 16 + aRow) * ROWB + ks * 32 + aSel;
                ldsm_x4(ah[mt][0], ah[mt][1], ah[mt][2], ah[mt][3], sb + SA_H + ra);
                ldsm_x4(al[mt][0], al[mt][1], al[mt][2], al[mt][3], sb + SA_L + ra);
            }
            #pragma unroll
            for (int ntp = 0; ntp < 2; ntp++) {
                uint32_t rb = (wn * 32 + ntp * 16 + bRow) * ROWB + ks * 32 + bSel;
                uint32_t h0, h1, h2, h3, l0, l1, l2, l3;
                ldsm_x4(h0, h1, h2, h3, sb + SB_H + rb);
                ldsm_x4(l0, l1, l2, l3, sb + SB_L + rb);
                #pragma unroll
                for (int mt = 0; mt < 2; mt++) {
                    float* c0 = c[mt][2 * ntp];
                    float* c1 = c[mt][2 * ntp + 1];
                    mma_bf16(c0, ah[mt], h0, h1);
                    mma_bf16(c0, ah[mt], l0, l1);
                    mma_bf16(c0, al[mt], h0, h1);
                    mma_bf16(c1, ah[mt], h2, h3);
                    mma_bf16(c1, ah[mt], l2, l3);
                    mma_bf16(c1, al[mt], h2, h3);
                }
            }
        }
        __syncthreads();
    }

    // epilogue.  mode 1 = GEMM1: q_lat cols scaled+tf32 -> g_mid, K cols tf32 -> g_mid,
    //            V cols (>=1088) bf16 hi/lo -> g_Vh/g_Vl.
    #pragma unroll
    for (int mt = 0; mt < 2; mt++) {
        int row0 = m0 + wm * 32 + mt * 16 + g;
        #pragma unroll
        for (int nt = 0; nt < 4; nt++) {
            int col = n0 + wn * 32 + nt * 8 + 2 * tig;
            float v0 = c[mt][nt][0], v1 = c[mt][nt][1];
            float v2 = c[mt][nt][2], v3 = c[mt][nt][3];
            if (mode == 1) {
                if (col < 1088) {
                    float sc = (col < 1024) ? 0.125f : 1.0f;
                    v0 = __uint_as_float(f2tf32(v0 * sc));
                    v1 = __uint_as_float(f2tf32(v1 * sc));
                    v2 = __uint_as_float(f2tf32(v2 * sc));
                    v3 = __uint_as_float(f2tf32(v3 * sc));
                    *(float2*)&C[(size_t)row0 * N + col]       = make_float2(v0, v1);
                    *(float2*)&C[(size_t)(row0 + 8) * N + col] = make_float2(v2, v3);
                } else {
                    int vc = col - 1088;
                    __nv_bfloat16 h0, l0, h1, l1;
                    bsplit(v0, h0, l0); bsplit(v1, h1, l1);
                    *(__nv_bfloat162*)&g_Vh[(size_t)row0 * 64 + vc] = __nv_bfloat162{h0, h1};
                    *(__nv_bfloat162*)&g_Vl[(size_t)row0 * 64 + vc] = __nv_bfloat162{l0, l1};
                    bsplit(v2, h0, l0); bsplit(v3, h1, l1);
                    *(__nv_bfloat162*)&g_Vh[(size_t)(row0 + 8) * 64 + vc] = __nv_bfloat162{h0, h1};
                    *(__nv_bfloat162*)&g_Vl[(size_t)(row0 + 8) * 64 + vc] = __nv_bfloat162{l0, l1};
                }
            } else {
                *(float2*)&C[(size_t)row0 * N + col]       = make_float2(v0, v1);
                *(float2*)&C[(size_t)(row0 + 8) * N + col] = make_float2(v2, v3);
            }
        }
    }
}

// ==================== flash attention: tf32 S + bf16 PV (register P-fragments) ========
// smem words: Qs[128][68] | 2 x { K[64][68] fp32, Vh[64][36w], Vl[64][36w] bf16 }
#define QS_OFF 0
#define KV_OFF (128 * 68)
#define KVW_K  0
#define KVW_VH 4352                  // 64*68
#define KVW_VL (KVW_VH + 64 * 36)    // 6656
#define KV_ST  (KVW_VL + 64 * 36)    // 8960 words per stage
#define ATTN_SMEM ((KV_OFF + 2 * KV_ST) * 4)    // 106496 B

__global__ __launch_bounds__(256, 2) void attn_mma() {
    extern __shared__ uint32_t sm[];
    const uint32_t sbase = smem_u32(sm);
    const int tid = threadIdx.x;
    const int wid = tid >> 5, lane = tid & 31;
    const int g = lane >> 2, tig = lane & 3;
    const int wq = wid * 16;
    const int qt = (int)gridDim.x - 1 - (int)blockIdx.x;  // heavy first
    const int h  = blockIdx.y;
    const int q0 = qt * 128;
    const int nkv = 2 * qt + 2;

    const uint32_t aRow = lane & 15;
    const uint32_t aSel = ((lane >> 4) & 1) * 16;
    const uint32_t bRow = (lane & 7) + ((lane & 16) ? 8 : 0);
    const uint32_t bSel = (lane & 8) ? 16 : 0;
    // ldmatrix.trans lane addressing for V
    const int vrow = lane & 7;
    const int vmk  = (lane >> 3) & 1;    // +8 k rows
    const int vmn  = (lane >> 4) & 1;    // +8 n cols

    auto fetch_kv = [&](int blk, int b) {
        const uint32_t st = sbase + (uint32_t)(KV_OFF + b * KV_ST) * 4u;
        #pragma unroll
        for (int i = 0; i < 4; i++) {       // K: 1024 chunks
            int idx = tid + i * 256;
            int r = idx >> 4, cc = (idx & 15) * 4;
            cp_async16(st + (uint32_t)(KVW_K + r * 68 + cc) * 4u,
                       &g_mid[(size_t)(blk * 64 + r) * NMID + 1024 + cc]);
        }
        #pragma unroll
        for (int i = 0; i < 4; i++) {       // Vh+Vl: 1024 chunks (16B = 8 bf16)
            int idx = tid + i * 256;
            int pl = idx >> 9;
            int r = (idx & 511) >> 3, cc = (idx & 7) * 8;
            const __nv_bfloat16* src = (pl ? g_Vl : g_Vh) + (size_t)(blk * 64 + r) * 64 + cc;
            cp_async16(st + (uint32_t)((pl ? KVW_VL : KVW_VH) + r * 36) * 4u + cc * 2u, src);
        }
        CP_COMMIT();
    };

    // prologue: KV block 0 + Q tile
    fetch_kv(0, 0);
    {
        #pragma unroll
        for (int i = 0; i < 8; i++) {
            int lin = tid + i * 256;
            int r = lin >> 4, c4 = lin & 15;
            cp_async16(sbase + (uint32_t)(QS_OFF + r * 68 + c4 * 4) * 4u,
                       &g_mid[(size_t)(q0 + r) * NMID + h * 64 + c4 * 4]);
        }
        CP_COMMIT();
    }
    CP_WAIT(0);
    __syncthreads();

    // preload Q A-fragments
    uint32_t qa[8][4];
    #pragma unroll
    for (int ks = 0; ks < 8; ks++) {
        uint32_t ra = sbase + (uint32_t)(QS_OFF + (wq + aRow) * 68 + ks * 8) * 4u + aSel;
        ldsm_x4(qa[ks][0], qa[ks][1], qa[ks][2], qa[ks][3], ra);
    }

    float o[8][4];
    #pragma unroll
    for (int nt = 0; nt < 8; nt++)
        #pragma unroll
        for (int j = 0; j < 4; j++) o[nt][j] = 0.f;
    float m0r = -1e30f, m1r = -1e30f, l0r = 0.f, l1r = 0.f;

    for (int kb = 0; kb < nkv; kb++) {
        const int buf = kb & 1;
        if (kb + 1 < nkv) { fetch_kv(kb + 1, buf ^ 1); CP_WAIT(1); }
        else              { CP_WAIT(0); }
        __syncthreads();

        const uint32_t stb = sbase + (uint32_t)(KV_OFF + buf * KV_ST) * 4u;
        const int s0 = kb * 64;

        // S = Q @ K^T
        float s[8][4];
        #pragma unroll
        for (int nt = 0; nt < 8; nt++)
            s[nt][0] = s[nt][1] = s[nt][2] = s[nt][3] = 0.f;
        #pragma unroll
        for (int ntp = 0; ntp < 4; ntp++) {
            #pragma unroll
            for (int ks = 0; ks < 8; ks++) {
                uint32_t addr = stb + (uint32_t)((ntp * 16 + bRow) * 68 + ks * 8) * 4u + bSel;
                uint32_t k0, k1, k2, k3;
                ldsm_x4(k0, k1, k2, k3, addr);
                mma_tf32(s[2 * ntp],     qa[ks], k0, k1);
                mma_tf32(s[2 * ntp + 1], qa[ks], k2, k3);
            }
        }

        // causal mask
        if (kb >= 2 * qt) {
            int row0 = q0 + wq + g, row1 = row0 + 8;
            #pragma unroll
            for (int nt = 0; nt < 8; nt++) {
                int c0 = s0 + nt * 8 + 2 * tig;
                if (c0     > row0) s[nt][0] = -1e30f;
                if (c0 + 1 > row0) s[nt][1] = -1e30f;
                if (c0     > row1) s[nt][2] = -1e30f;
                if (c0 + 1 > row1) s[nt][3] = -1e30f;
            }
        }

        // online softmax
        float rm0 = -1e30f, rm1 = -1e30f;
        #pragma unroll
        for (int nt = 0; nt < 8; nt++) {
            rm0 = fmaxf(rm0, fmaxf(s[nt][0], s[nt][1]));
            rm1 = fmaxf(rm1, fmaxf(s[nt][2], s[nt][3]));
        }
        rm0 = fmaxf(rm0, __shfl_xor_sync(0xffffffffu, rm0, 1));
        rm0 = fmaxf(rm0, __shfl_xor_sync(0xffffffffu, rm0, 2));
        rm1 = fmaxf(rm1, __shfl_xor_sync(0xffffffffu, rm1, 1));
        rm1 = fmaxf(rm1, __shfl_xor_sync(0xffffffffu, rm1, 2));
        float mn0 = fmaxf(m0r, rm0), mn1 = fmaxf(m1r, rm1);
        float al0 = __expf(m0r - mn0), al1 = __expf(m1r - mn1);
        m0r = mn0; m1r = mn1;

        float rs0 = 0.f, rs1 = 0.f;
        #pragma unroll
        for (int nt = 0; nt < 8; nt++) {
            s[nt][0] = __expf(s[nt][0] - mn0); rs0 += s[nt][0];
            s[nt][1] = __expf(s[nt][1] - mn0); rs0 += s[nt][1];
            s[nt][2] = __expf(s[nt][2] - mn1); rs1 += s[nt][2];
            s[nt][3] = __expf(s[nt][3] - mn1); rs1 += s[nt][3];
        }
        rs0 += __shfl_xor_sync(0xffffffffu, rs0, 1);
        rs0 += __shfl_xor_sync(0xffffffffu, rs0, 2);
        rs1 += __shfl_xor_sync(0xffffffffu, rs1, 1);
        rs1 += __shfl_xor_sync(0xffffffffu, rs1, 2);
        l0r = l0r * al0 + rs0;
        l1r = l1r * al1 + rs1;

        // O = O*alpha + P @ V   (P = Ph+Pl in registers; V = Vh+Vl via ldmatrix.trans)
        #pragma unroll
        for (int nt = 0; nt < 8; nt++) {
            o[nt][0] *= al0; o[nt][1] *= al0;
            o[nt][2] *= al1; o[nt][3] *= al1;
        }
        #pragma unroll
        for (int ks = 0; ks < 4; ks++) {
            uint32_t pah[4], pal[4];
            {
                const float* se = s[2 * ks];
                const float* so = s[2 * ks + 1];
                pah[0] = packbf(se[0], se[1]);
                pah[1] = packbf(se[2], se[3]);
                pah[2] = packbf(so[0], so[1]);
                pah[3] = packbf(so[2], so[3]);
                float p0 = se[0] - __bfloat162float(__float2bfloat16_rn(se[0]));
                float p1 = se[1] - __bfloat162float(__float2bfloat16_rn(se[1]));
                float p2 = se[2] - __bfloat162float(__float2bfloat16_rn(se[2]));
                float p3 = se[3] - __bfloat162float(__float2bfloat16_rn(se[3]));
                pal[0] = packbf(p0, p1);
                pal[1] = packbf(p2, p3);
                p0 = so[0] - __bfloat162float(__float2bfloat16_rn(so[0]));
                p1 = so[1] - __bfloat162float(__float2bfloat16_rn(so[1]));
                p2 = so[2] - __bfloat162float(__float2bfloat16_rn(so[2]));
                p3 = so[3] - __bfloat162float(__float2bfloat16_rn(so[3]));
                pal[2] = packbf(p0, p1);
                pal[3] = packbf(p2, p3);
            }
            #pragma unroll
            for (int ntp = 0; ntp < 4; ntp++) {
                uint32_t rowk = ks * 16 + vmk * 8 + vrow;
                uint32_t coln = ntp * 16 + vmn * 8;
                uint32_t ha = stb + (uint32_t)(KVW_VH + rowk * 36) * 4u + coln * 2u;
                uint32_t la = stb + (uint32_t)(KVW_VL + rowk * 36) * 4u + coln * 2u;
                uint32_t vh0, vh1, vh2, vh3, vl0, vl1, vl2, vl3;
                ldsm_x4_t(vh0, vh1, vh2, vh3, ha);
                ldsm_x4_t(vl0, vl1, vl2, vl3, la);
                float* c0 = o[2 * ntp];
                float* c1 = o[2 * ntp + 1];
                mma_bf16(c0, pah, vh0, vh1);
                mma_bf16(c0, pah, vl0, vl1);
                mma_bf16(c0, pal, vh0, vh1);
                mma_bf16(c1, pah, vh2, vh3);
                mma_bf16(c1, pah, vl2, vl3);
                mma_bf16(c1, pal, vh2, vh3);
            }
        }
        __syncthreads();
    }

    // normalize + write ctx
    float inv0 = 1.0f / l0r, inv1 = 1.0f / l1r;
    int row0 = q0 + wq + g;
    #pragma unroll
    for (int nt = 0; nt < 8; nt++) {
        int col = h * 64 + nt * 8 + 2 * tig;
        *(float2*)&g_ctx[(size_t)row0 * E_DIM + col] =
            make_float2(o[nt][0] * inv0, o[nt][1] * inv0);
        *(float2*)&g_ctx[(size_t)(row0 + 8) * E_DIM + col] =
            make_float2(o[nt][2] * inv1, o[nt][3] * inv1);
    }
}

// ---------------- launch ----------------
extern "C" void kernel_launch(void* const* d_in, const int* in_sizes, int n_in,
                              void* d_out, int out_size) {
    const float* hidden = (const float*)d_in[0];
    const float* Wq     = (const float*)d_in[1];
    const float* Wk     = (const float*)d_in[2];
    const float* Wv     = (const float*)d_in[3];
    const float* q2l    = (const float*)d_in[4];
    const float* vup    = (const float*)d_in[5];
    const float* Wout   = (const float*)d_in[6];
    float* out = (float*)d_out;

    void *w1h, *w1l, *w2h, *w2l, *ah, *al, *midp, *ctxp;
    cudaGetSymbolAddress(&w1h, g_W1Th); cudaGetSymbolAddress(&w1l, g_W1Tl);
    cudaGetSymbolAddress(&w2h, g_W2Th); cudaGetSymbolAddress(&w2l, g_W2Tl);
    cudaGetSymbolAddress(&ah,  g_Ah);   cudaGetSymbolAddress(&al,  g_Al);
    cudaGetSymbolAddress(&midp, g_mid); cudaGetSymbolAddress(&ctxp, g_ctx);

    cudaFuncSetAttribute(gemm_bf3, cudaFuncAttributeMaxDynamicSharedMemorySize, GEMM_SMEM);
    cudaFuncSetAttribute(attn_mma, cudaFuncAttributeMaxDynamicSharedMemorySize, ATTN_SMEM);

    prep_w1_kernel<<<dim3(16, 16), 256>>>(Wq, q2l);
    prep_kv_kernel<<<256, 256>>>(Wk, Wv);
    prep_w2_kernel<<<dim3(16, 16), 256>>>(vup, Wout);

    split_kernel<<<T_SEQ * E_DIM / 1024, 256>>>(hidden, (__nv_bfloat16*)ah, (__nv_bfloat16*)al);

    gemm_bf3<<<dim3(NMID / 64, T_SEQ / 128), 256, GEMM_SMEM>>>(
        (const __nv_bfloat16*)ah, (const __nv_bfloat16*)al,
        (const __nv_bfloat16*)w1h, (const __nv_bfloat16*)w1l,
        (float*)midp, NMID, E_DIM, 1);

    attn_mma<<<dim3(T_SEQ / 128, H_NUM), 256, ATTN_SMEM>>>();

    split_kernel<<<T_SEQ * E_DIM / 1024, 256>>>((const float*)ctxp,
                                                (__nv_bfloat16*)ah, (__nv_bfloat16*)al);

    gemm_bf3<<<dim3(E_DIM / 64, T_SEQ / 128), 256, GEMM_SMEM>>>(
        (const __nv_bfloat16*)ah, (const __nv_bfloat16*)al,
        (const __nv_bfloat16*)w2h, (const __nv_bfloat16*)w2l,
        out, E_DIM, E_DIM, 0);
}

// round 10
// speedup vs baseline: 1.3486x; 1.3486x over previous
#include <cuda_runtime.h>
#include <cuda_bf16.h>
#include <cuda_fp16.h>
#include <cstdint>

#define T_SEQ 2048
#define E_DIM 1024
#define H_NUM 16
#define L_DIM 64
#define NMID  1152   // 1024 q_lat cols + 64 latent_k + 64 latent_v

// ==================== helpers ====================
// bf16: D(16x8) += A(16x16) * B(16x8)
__device__ __forceinline__ void mma_bf16(float* c, const uint32_t* a, uint32_t b0, uint32_t b1) {
    asm volatile(
        "mma.sync.aligned.m16n8k16.row.col.f32.bf16.bf16.f32 "
        "{%0,%1,%2,%3}, {%4,%5,%6,%7}, {%8,%9}, {%0,%1,%2,%3};"
        : "+f"(c[0]), "+f"(c[1]), "+f"(c[2]), "+f"(c[3])
        : "r"(a[0]), "r"(a[1]), "r"(a[2]), "r"(a[3]), "r"(b0), "r"(b1));
}

// fp16: D(16x8) += A(16x16) * B(16x8)  (f32 accumulate)
__device__ __forceinline__ void mma_f16(float* c, const uint32_t* a, uint32_t b0, uint32_t b1) {
    asm volatile(
        "mma.sync.aligned.m16n8k16.row.col.f32.f16.f16.f32 "
        "{%0,%1,%2,%3}, {%4,%5,%6,%7}, {%8,%9}, {%0,%1,%2,%3};"
        : "+f"(c[0]), "+f"(c[1]), "+f"(c[2]), "+f"(c[3])
        : "r"(a[0]), "r"(a[1]), "r"(a[2]), "r"(a[3]), "r"(b0), "r"(b1));
}

__device__ __forceinline__ void ldsm_x4(uint32_t& r0, uint32_t& r1, uint32_t& r2, uint32_t& r3,
                                        uint32_t addr) {
    asm volatile("ldmatrix.sync.aligned.m8n8.x4.shared.b16 {%0,%1,%2,%3}, [%4];"
                 : "=r"(r0), "=r"(r1), "=r"(r2), "=r"(r3) : "r"(addr));
}

__device__ __forceinline__ void ldsm_x4_t(uint32_t& r0, uint32_t& r1, uint32_t& r2, uint32_t& r3,
                                          uint32_t addr) {
    asm volatile("ldmatrix.sync.aligned.m8n8.x4.trans.shared.b16 {%0,%1,%2,%3}, [%4];"
                 : "=r"(r0), "=r"(r1), "=r"(r2), "=r"(r3) : "r"(addr));
}

__device__ __forceinline__ uint32_t smem_u32(const void* p) {
    uint32_t a;
    asm("{ .reg .u64 t; cvta.to.shared.u64 t, %1; cvt.u32.u64 %0, t; }" : "=r"(a) : "l"(p));
    return a;
}

__device__ __forceinline__ void cp_async16(uint32_t dst, const void* src) {
    asm volatile("cp.async.cg.shared.global [%0], [%1], 16;" :: "r"(dst), "l"(src));
}
#define CP_COMMIT()  asm volatile("cp.async.commit_group;" ::: "memory")
#define CP_WAIT(N)   asm volatile("cp.async.wait_group %0;" :: "n"(N) : "memory")

__device__ __forceinline__ void bsplit(float x, __nv_bfloat16& h, __nv_bfloat16& l) {
    h = __float2bfloat16_rn(x);
    l = __float2bfloat16_rn(x - __bfloat162float(h));
}

__device__ __forceinline__ uint32_t packh(float a, float b) {
    __half2 t = __floats2half2_rn(a, b);
    return *(uint32_t*)&t;
}

// ==================== device scratch ====================
__device__ __nv_bfloat16 g_W1Th[NMID * E_DIM], g_W1Tl[NMID * E_DIM];
__device__ __nv_bfloat16 g_W2Th[E_DIM * E_DIM], g_W2Tl[E_DIM * E_DIM];
__device__ __nv_bfloat16 g_Ah[T_SEQ * E_DIM],  g_Al[T_SEQ * E_DIM];
__device__ __half g_Q[T_SEQ * 1024];   // q_lat * 0.125, fp16
__device__ __half g_K[T_SEQ * 64];     // latent_k, fp16
__device__ __half g_V[T_SEQ * 64];     // latent_v, fp16
__device__ float  g_ctx[T_SEQ * E_DIM];

// ---------------- split A: bf16 hi/lo decomposition ----------------
__global__ __launch_bounds__(256) void split_kernel(const float* __restrict__ src,
                                                    __nv_bfloat16* __restrict__ hi,
                                                    __nv_bfloat16* __restrict__ lo) {
    int i = (blockIdx.x * 256 + threadIdx.x) * 4;
    float4 v = *(const float4*)&src[i];
    __nv_bfloat16 h[4], l[4];
    bsplit(v.x, h[0], l[0]); bsplit(v.y, h[1], l[1]);
    bsplit(v.z, h[2], l[2]); bsplit(v.w, h[3], l[3]);
    *(__nv_bfloat162*)&hi[i]     = __nv_bfloat162{h[0], h[1]};
    *(__nv_bfloat162*)&hi[i + 2] = __nv_bfloat162{h[2], h[3]};
    *(__nv_bfloat162*)&lo[i]     = __nv_bfloat162{l[0], l[1]};
    *(__nv_bfloat162*)&lo[i + 2] = __nv_bfloat162{l[2], l[3]};
}

// ---------------- prep 1 ----------------
__global__ __launch_bounds__(256) void prep_w1_kernel(const float* __restrict__ Wq,
                                                      const float* __restrict__ q2l) {
    __shared__ float Wqs[64][65];
    __shared__ float Qls[64][65];
    const int h  = blockIdx.y;
    const int e0 = blockIdx.x * 64;
    const int tid = threadIdx.x, tx = tid & 15, ty = tid >> 4;

    #pragma unroll
    for (int i = 0; i < 16; i++) {
        int lin = tid + i * 256;
        int c = lin & 63, r = lin >> 6;
        Wqs[r][c] = Wq[(h * 64 + r) * E_DIM + e0 + c];
        Qls[r][c] = q2l[(h * 64 + r) * 64 + c];
    }
    __syncthreads();

    float acc[4][4];
    #pragma unroll
    for (int i = 0; i < 4; i++)
        #pragma unroll
        for (int j = 0; j < 4; j++) acc[i][j] = 0.f;

    #pragma unroll 8
    for (int d = 0; d < 64; d++) {
        float a[4], b[4];
        #pragma unroll
        for (int i = 0; i < 4; i++) a[i] = Wqs[d][ty * 4 + i];
        #pragma unroll
        for (int j = 0; j < 4; j++) b[j] = Qls[d][tx * 4 + j];
        #pragma unroll
        for (int i = 0; i < 4; i++)
            #pragma unroll
            for (int j = 0; j < 4; j++) acc[i][j] += a[i] * b[j];
    }
    #pragma unroll
    for (int j = 0; j < 4; j++)
        #pragma unroll
        for (int i = 0; i < 4; i++) {
            int idx = (h * 64 + tx * 4 + j) * E_DIM + e0 + ty * 4 + i;
            __nv_bfloat16 hf, lf; bsplit(acc[i][j], hf, lf);
            g_W1Th[idx] = hf; g_W1Tl[idx] = lf;
        }
}

// ---------------- prep 2 ----------------
__global__ __launch_bounds__(256) void prep_kv_kernel(const float* __restrict__ Wk,
                                                      const float* __restrict__ Wv) {
    int idx = blockIdx.x * 256 + threadIdx.x;   // 64 * 1024
    __nv_bfloat16 hf, lf;
    bsplit(Wk[idx], hf, lf);
    g_W1Th[1024 * E_DIM + idx] = hf; g_W1Tl[1024 * E_DIM + idx] = lf;
    bsplit(Wv[idx], hf, lf);
    g_W1Th[1088 * E_DIM + idx] = hf; g_W1Tl[1088 * E_DIM + idx] = lf;
}

// ---------------- prep 3 ----------------
__global__ __launch_bounds__(256) void prep_w2_kernel(const float* __restrict__ vup,
                                                      const float* __restrict__ Wout) {
    __shared__ __align__(16) float Wos[64][68];
    __shared__ __align__(16) float Vus[64][68];
    const int h  = blockIdx.y;
    const int e0 = blockIdx.x * 64;
    const int tid = threadIdx.x, tx = tid & 15, ty = tid >> 4;

    #pragma unroll
    for (int i = 0; i < 16; i++) {
        int lin = tid + i * 256;
        int c = lin & 63, r = lin >> 6;
        Wos[r][c] = Wout[(e0 + r) * E_DIM + h * 64 + c];
        Vus[r][c] = vup[(h * 64 + r) * 64 + c];
    }
    __syncthreads();

    float acc[4][4];
    #pragma unroll
    for (int i = 0; i < 4; i++)
        #pragma unroll
        for (int j = 0; j < 4; j++) acc[i][j] = 0.f;

    #pragma unroll
    for (int d4 = 0; d4 < 16; d4++) {
        float4 a[4], b[4];
        #pragma unroll
        for (int i = 0; i < 4; i++) a[i] = *(const float4*)&Vus[ty * 4 + i][d4 * 4];
        #pragma unroll
        for (int j = 0; j < 4; j++) b[j] = *(const float4*)&Wos[tx * 4 + j][d4 * 4];
        #pragma unroll
        for (int i = 0; i < 4; i++)
            #pragma unroll
            for (int j = 0; j < 4; j++)
                acc[i][j] += a[i].x * b[j].x + a[i].y * b[j].y +
                             a[i].z * b[j].z + a[i].w * b[j].w;
    }
    #pragma unroll
    for (int j = 0; j < 4; j++)
        #pragma unroll
        for (int i = 0; i < 4; i++) {
            int idx = (e0 + tx * 4 + j) * E_DIM + h * 64 + ty * 4 + i;
            __nv_bfloat16 hf, lf; bsplit(acc[i][j], hf, lf);
            g_W2Th[idx] = hf; g_W2Tl[idx] = lf;
        }
}

// ==================== bf16 3-term mma.sync GEMM (R8, epilogue mode 1 new) ============
#define ROWB 80
#define SA_H 0
#define SA_L (128 * ROWB)
#define SB_H (2 * 128 * ROWB)
#define SB_L (SB_H + 64 * ROWB)
#define SSZ  (SB_L + 64 * ROWB)
#define GEMM_SMEM (2 * SSZ)

__global__ __launch_bounds__(256, 2) void gemm_bf3(const __nv_bfloat16* __restrict__ Ah,
                                                   const __nv_bfloat16* __restrict__ Al,
                                                   const __nv_bfloat16* __restrict__ Bh,
                                                   const __nv_bfloat16* __restrict__ Bl,
                                                   float* __restrict__ C,
                                                   int N, int K, int mode) {
    extern __shared__ char gsm[];
    const uint32_t sbase = smem_u32(gsm);

    const int tid = threadIdx.x;
    const int wid = tid >> 5, lane = tid & 31;
    const int g = lane >> 2, tig = lane & 3;
    const int wm = wid & 3, wn = wid >> 2;
    const int m0 = blockIdx.y * 128;
    const int n0 = blockIdx.x * 64;
    const int nst = K >> 5;

    const uint32_t aRow = lane & 15;
    const uint32_t aSel = ((lane >> 4) & 1) * 16;
    const uint32_t bRow = (lane & 7) + ((lane & 16) ? 8 : 0);
    const uint32_t bSel = (lane & 8) ? 16 : 0;

    float c[2][4][4];
    #pragma unroll
    for (int mt = 0; mt < 2; mt++)
        #pragma unroll
        for (int nt = 0; nt < 4; nt++)
            #pragma unroll
            for (int j = 0; j < 4; j++) c[mt][nt][j] = 0.f;

    auto fetch = [&](int k0, int b) {
        const uint32_t s0 = sbase + (uint32_t)(b * SSZ);
        #pragma unroll
        for (int i = 0; i < 6; i++) {
            int idx = tid + i * 256;
            if (idx < 1024) {
                int t = idx >> 9;
                int r = (idx & 511) >> 2, cc = idx & 3;
                const __nv_bfloat16* src = (t ? Al : Ah) + (size_t)(m0 + r) * K + k0 + cc * 8;
                cp_async16(s0 + (t ? SA_L : SA_H) + r * ROWB + cc * 16, src);
            } else {
                int t = (idx - 1024) >> 8;
                int r = ((idx - 1024) & 255) >> 2, cc = idx & 3;
                const __nv_bfloat16* src = (t ? Bl : Bh) + (size_t)(n0 + r) * K + k0 + cc * 8;
                cp_async16(s0 + (t ? SB_L : SB_H) + r * ROWB + cc * 16, src);
            }
        }
        CP_COMMIT();
    };

    fetch(0, 0);

    for (int s = 0; s < nst; s++) {
        const int buf = s & 1;
        if (s + 1 < nst) { fetch((s + 1) << 5, buf ^ 1); CP_WAIT(1); }
        else             { CP_WAIT(0); }
        __syncthreads();

        const uint32_t sb = sbase + (uint32_t)(buf * SSZ);
        #pragma unroll
        for (int ks = 0; ks < 2; ks++) {
            uint32_t ah[2][4], al[2][4];
            #pragma unroll
            for (int mt = 0; mt < 2; mt++) {
                uint32_t ra = (wm * 32 + mt * 16 + aRow) * ROWB + ks * 32 + aSel;
                ldsm_x4(ah[mt][0], ah[mt][1], ah[mt][2], ah[mt][3], sb + SA_H + ra);
                ldsm_x4(al[mt][0], al[mt][1], al[mt][2], al[mt][3], sb + SA_L + ra);
            }
            #pragma unroll
            for (int ntp = 0; ntp < 2; ntp++) {
                uint32_t rb = (wn * 32 + ntp * 16 + bRow) * ROWB + ks * 32 + bSel;
                uint32_t h0, h1, h2, h3, l0, l1, l2, l3;
                ldsm_x4(h0, h1, h2, h3, sb + SB_H + rb);
                ldsm_x4(l0, l1, l2, l3, sb + SB_L + rb);
                #pragma unroll
                for (int mt = 0; mt < 2; mt++) {
                    float* c0 = c[mt][2 * ntp];
                    float* c1 = c[mt][2 * ntp + 1];
                    mma_bf16(c0, ah[mt], h0, h1);
                    mma_bf16(c0, ah[mt], l0, l1);
                    mma_bf16(c0, al[mt], h0, h1);
                    mma_bf16(c1, ah[mt], h2, h3);
                    mma_bf16(c1, ah[mt], l2, l3);
                    mma_bf16(c1, al[mt], h2, h3);
                }
            }
        }
        __syncthreads();
    }

    // epilogue.  mode 1 = GEMM1: q_lat -> g_Q fp16 (x0.125), K -> g_K fp16, V -> g_V fp16
    #pragma unroll
    for (int mt = 0; mt < 2; mt++) {
        int row0 = m0 + wm * 32 + mt * 16 + g;
        #pragma unroll
        for (int nt = 0; nt < 4; nt++) {
            int col = n0 + wn * 32 + nt * 8 + 2 * tig;
            float v0 = c[mt][nt][0], v1 = c[mt][nt][1];
            float v2 = c[mt][nt][2], v3 = c[mt][nt][3];
            if (mode == 1) {
                if (col < 1024) {
                    *(uint32_t*)&g_Q[(size_t)row0 * 1024 + col] =
                        packh(v0 * 0.125f, v1 * 0.125f);
                    *(uint32_t*)&g_Q[(size_t)(row0 + 8) * 1024 + col] =
                        packh(v2 * 0.125f, v3 * 0.125f);
                } else if (col < 1088) {
                    int kc = col - 1024;
                    *(uint32_t*)&g_K[(size_t)row0 * 64 + kc]       = packh(v0, v1);
                    *(uint32_t*)&g_K[(size_t)(row0 + 8) * 64 + kc] = packh(v2, v3);
                } else {
                    int vc = col - 1088;
                    *(uint32_t*)&g_V[(size_t)row0 * 64 + vc]       = packh(v0, v1);
                    *(uint32_t*)&g_V[(size_t)(row0 + 8) * 64 + vc] = packh(v2, v3);
                }
            } else {
                *(float2*)&C[(size_t)row0 * N + col]       = make_float2(v0, v1);
                *(float2*)&C[(size_t)(row0 + 8) * N + col] = make_float2(v2, v3);
            }
        }
    }
}

// ==================== fp16 flash attention (register P, ldmatrix everywhere) ==========
// CTA: 128-query tile, 8 warps x 16 rows, KV tiles 64, L=64, fp16 fragments, f32 accum.
// smem bytes: Q[128][144B] | 2 x { K[64][144B], V[64][144B] }
#define AROW 144                       // padded row bytes (64 fp16 = 128B data)
#define AQ_B 0
#define AKV_B (128 * AROW)             // 18432
#define AST_B (2 * 64 * AROW)          // stage: K + V = 18432
#define AV_B  (64 * AROW)              // V offset inside stage
#define ATTN_SMEM (AKV_B + 2 * AST_B)  // 55296

__global__ __launch_bounds__(256, 2) void attn_mma() {
    extern __shared__ char asm_[];
    const uint32_t sbase = smem_u32(asm_);
    const int tid = threadIdx.x;
    const int wid = tid >> 5, lane = tid & 31;
    const int g = lane >> 2, tig = lane & 3;
    const int wq = wid * 16;
    const int qt = (int)gridDim.x - 1 - (int)blockIdx.x;  // heavy first
    const int h  = blockIdx.y;
    const int q0 = qt * 128;
    const int nkv = 2 * qt + 2;

    // ldmatrix lane addressing (patterns validated R8/R9)
    const uint32_t aRow = lane & 15;                      // A (Q)
    const uint32_t aSel = ((lane >> 4) & 1) * 16;
    const uint32_t bRow = (lane & 7) + ((lane & 16) ? 8 : 0);   // B (K)
    const uint32_t bSel = (lane & 8) ? 16 : 0;
    const int vrow = lane & 7;                            // B-trans (V)
    const int vmk  = (lane >> 3) & 1;
    const int vmn  = (lane >> 4) & 1;

    auto fetch_kv = [&](int blk, int b) {
        const uint32_t st = sbase + (uint32_t)(AKV_B + b * AST_B);
        #pragma unroll
        for (int i = 0; i < 4; i++) {     // 1024 chunks: K 512 + V 512
            int idx = tid + i * 256;
            int isV = idx >> 9;
            int r = (idx & 511) >> 3, cc = idx & 7;
            const __half* src = (isV ? g_V : g_K) + (size_t)(blk * 64 + r) * 64 + cc * 8;
            cp_async16(st + (isV ? AV_B : 0) + r * AROW + cc * 16, src);
        }
        CP_COMMIT();
    };

    // prologue: KV block 0 + Q tile
    fetch_kv(0, 0);
    {
        #pragma unroll
        for (int i = 0; i < 4; i++) {     // 1024 chunks
            int idx = tid + i * 256;
            int r = idx >> 3, cc = idx & 7;
            cp_async16(sbase + (uint32_t)(AQ_B + r * AROW + cc * 16),
                       &g_Q[(size_t)(q0 + r) * 1024 + h * 64 + cc * 8]);
        }
        CP_COMMIT();
    }
    CP_WAIT(0);
    __syncthreads();

    // preload Q A-fragments: 4 k-steps (k16 each)
    uint32_t qa[4][4];
    #pragma unroll
    for (int ks = 0; ks < 4; ks++) {
        uint32_t ra = sbase + (uint32_t)(AQ_B + (wq + aRow) * AROW + ks * 32) + aSel;
        ldsm_x4(qa[ks][0], qa[ks][1], qa[ks][2], qa[ks][3], ra);
    }

    float o[8][4];
    #pragma unroll
    for (int nt = 0; nt < 8; nt++)
        #pragma unroll
        for (int j = 0; j < 4; j++) o[nt][j] = 0.f;
    float m0r = -1e30f, m1r = -1e30f, l0r = 0.f, l1r = 0.f;

    for (int kb = 0; kb < nkv; kb++) {
        const int buf = kb & 1;
        if (kb + 1 < nkv) { fetch_kv(kb + 1, buf ^ 1); CP_WAIT(1); }
        else              { CP_WAIT(0); }
        __syncthreads();

        const uint32_t stb = sbase + (uint32_t)(AKV_B + buf * AST_B);
        const int s0 = kb * 64;

        // S = Q @ K^T : 16 ldsm.x4 + 32 fp16 MMA
        float s[8][4];
        #pragma unroll
        for (int nt = 0; nt < 8; nt++)
            s[nt][0] = s[nt][1] = s[nt][2] = s[nt][3] = 0.f;
        #pragma unroll
        for (int ntp = 0; ntp < 4; ntp++) {
            #pragma unroll
            for (int ks = 0; ks < 4; ks++) {
                uint32_t addr = stb + (uint32_t)((ntp * 16 + bRow) * AROW + ks * 32) + bSel;
                uint32_t k0, k1, k2, k3;
                ldsm_x4(k0, k1, k2, k3, addr);
                mma_f16(s[2 * ntp],     qa[ks], k0, k1);
                mma_f16(s[2 * ntp + 1], qa[ks], k2, k3);
            }
        }

        // causal mask
        if (kb >= 2 * qt) {
            int row0 = q0 + wq + g, row1 = row0 + 8;
            #pragma unroll
            for (int nt = 0; nt < 8; nt++) {
                int c0 = s0 + nt * 8 + 2 * tig;
                if (c0     > row0) s[nt][0] = -1e30f;
                if (c0 + 1 > row0) s[nt][1] = -1e30f;
                if (c0     > row1) s[nt][2] = -1e30f;
                if (c0 + 1 > row1) s[nt][3] = -1e30f;
            }
        }

        // online softmax
        float rm0 = -1e30f, rm1 = -1e30f;
        #pragma unroll
        for (int nt = 0; nt < 8; nt++) {
            rm0 = fmaxf(rm0, fmaxf(s[nt][0], s[nt][1]));
            rm1 = fmaxf(rm1, fmaxf(s[nt][2], s[nt][3]));
        }
        rm0 = fmaxf(rm0, __shfl_xor_sync(0xffffffffu, rm0, 1));
        rm0 = fmaxf(rm0, __shfl_xor_sync(0xffffffffu, rm0, 2));
        rm1 = fmaxf(rm1, __shfl_xor_sync(0xffffffffu, rm1, 1));
        rm1 = fmaxf(rm1, __shfl_xor_sync(0xffffffffu, rm1, 2));
        float mn0 = fmaxf(m0r, rm0), mn1 = fmaxf(m1r, rm1);
        float al0 = __expf(m0r - mn0), al1 = __expf(m1r - mn1);
        m0r = mn0; m1r = mn1;

        float rs0 = 0.f, rs1 = 0.f;
        #pragma unroll
        for (int nt = 0; nt < 8; nt++) {
            s[nt][0] = __expf(s[nt][0] - mn0); rs0 += s[nt][0];
            s[nt][1] = __expf(s[nt][1] - mn0); rs0 += s[nt][1];
            s[nt][2] = __expf(s[nt][2] - mn1); rs1 += s[nt][2];
            s[nt][3] = __expf(s[nt][3] - mn1); rs1 += s[nt][3];
        }
        rs0 += __shfl_xor_sync(0xffffffffu, rs0, 1);
        rs0 += __shfl_xor_sync(0xffffffffu, rs0, 2);
        rs1 += __shfl_xor_sync(0xffffffffu, rs1, 1);
        rs1 += __shfl_xor_sync(0xffffffffu, rs1, 2);
        l0r = l0r * al0 + rs0;
        l1r = l1r * al1 + rs1;

        // O = O*alpha + P @ V : P in registers (fp16 packs), V via ldmatrix.trans
        #pragma unroll
        for (int nt = 0; nt < 8; nt++) {
            o[nt][0] *= al0; o[nt][1] *= al0;
            o[nt][2] *= al1; o[nt][3] *= al1;
        }
        #pragma unroll
        for (int ks = 0; ks < 4; ks++) {
            uint32_t pa[4];
            pa[0] = packh(s[2 * ks][0],     s[2 * ks][1]);
            pa[1] = packh(s[2 * ks][2],     s[2 * ks][3]);
            pa[2] = packh(s[2 * ks + 1][0], s[2 * ks + 1][1]);
            pa[3] = packh(s[2 * ks + 1][2], s[2 * ks + 1][3]);
            #pragma unroll
            for (int ntp = 0; ntp < 4; ntp++) {
                uint32_t rowk = ks * 16 + vmk * 8 + vrow;
                uint32_t coln = ntp * 16 + vmn * 8;
                uint32_t va = stb + AV_B + rowk * AROW + coln * 2;
                uint32_t v0, v1, v2, v3;
                ldsm_x4_t(v0, v1, v2, v3, va);
                mma_f16(o[2 * ntp],     pa, v0, v1);
                mma_f16(o[2 * ntp + 1], pa, v2, v3);
            }
        }
        __syncthreads();
    }

    // normalize + write ctx
    float inv0 = 1.0f / l0r, inv1 = 1.0f / l1r;
    int row0 = q0 + wq + g;
    #pragma unroll
    for (int nt = 0; nt < 8; nt++) {
        int col = h * 64 + nt * 8 + 2 * tig;
        *(float2*)&g_ctx[(size_t)row0 * E_DIM + col] =
            make_float2(o[nt][0] * inv0, o[nt][1] * inv0);
        *(float2*)&g_ctx[(size_t)(row0 + 8) * E_DIM + col] =
            make_float2(o[nt][2] * inv1, o[nt][3] * inv1);
    }
}

// ---------------- launch ----------------
extern "C" void kernel_launch(void* const* d_in, const int* in_sizes, int n_in,
                              void* d_out, int out_size) {
    const float* hidden = (const float*)d_in[0];
    const float* Wq     = (const float*)d_in[1];
    const float* Wk     = (const float*)d_in[2];
    const float* Wv     = (const float*)d_in[3];
    const float* q2l    = (const float*)d_in[4];
    const float* vup    = (const float*)d_in[5];
    const float* Wout   = (const float*)d_in[6];
    float* out = (float*)d_out;

    void *w1h, *w1l, *w2h, *w2l, *ah, *al, *ctxp;
    cudaGetSymbolAddress(&w1h, g_W1Th); cudaGetSymbolAddress(&w1l, g_W1Tl);
    cudaGetSymbolAddress(&w2h, g_W2Th); cudaGetSymbolAddress(&w2l, g_W2Tl);
    cudaGetSymbolAddress(&ah,  g_Ah);   cudaGetSymbolAddress(&al,  g_Al);
    cudaGetSymbolAddress(&ctxp, g_ctx);

    cudaFuncSetAttribute(gemm_bf3, cudaFuncAttributeMaxDynamicSharedMemorySize, GEMM_SMEM);
    cudaFuncSetAttribute(attn_mma, cudaFuncAttributeMaxDynamicSharedMemorySize, ATTN_SMEM);

    prep_w1_kernel<<<dim3(16, 16), 256>>>(Wq, q2l);
    prep_kv_kernel<<<256, 256>>>(Wk, Wv);
    prep_w2_kernel<<<dim3(16, 16), 256>>>(vup, Wout);

    split_kernel<<<T_SEQ * E_DIM / 1024, 256>>>(hidden, (__nv_bfloat16*)ah, (__nv_bfloat16*)al);

    // GEMM1: epilogue emits fp16 Q/K/V directly (mode 1)
    gemm_bf3<<<dim3(NMID / 64, T_SEQ / 128), 256, GEMM_SMEM>>>(
        (const __nv_bfloat16*)ah, (const __nv_bfloat16*)al,
        (const __nv_bfloat16*)w1h, (const __nv_bfloat16*)w1l,
        (float*)ctxp /*unused in mode 1*/, NMID, E_DIM, 1);

    attn_mma<<<dim3(T_SEQ / 128, H_NUM), 256, ATTN_SMEM>>>();

    split_kernel<<<T_SEQ * E_DIM / 1024, 256>>>((const float*)ctxp,
                                                (__nv_bfloat16*)ah, (__nv_bfloat16*)al);

    gemm_bf3<<<dim3(E_DIM / 64, T_SEQ / 128), 256, GEMM_SMEM>>>(
        (const __nv_bfloat16*)ah, (const __nv_bfloat16*)al,
        (const __nv_bfloat16*)w2h, (const __nv_bfloat16*)w2l,
        out, E_DIM, E_DIM, 0);
}

// round 11
// speedup vs baseline: 1.3919x; 1.0321x over previous
#include <cuda_runtime.h>
#include <cuda_bf16.h>
#include <cuda_fp16.h>
#include <cstdint>

#define T_SEQ 2048
#define E_DIM 1024
#define H_NUM 16
#define L_DIM 64
#define NMID  1152   // 1024 q_lat cols + 64 latent_k + 64 latent_v

// ==================== helpers ====================
// bf16: D(16x8) += A(16x16) * B(16x8)
__device__ __forceinline__ void mma_bf16(float* c, const uint32_t* a, uint32_t b0, uint32_t b1) {
    asm volatile(
        "mma.sync.aligned.m16n8k16.row.col.f32.bf16.bf16.f32 "
        "{%0,%1,%2,%3}, {%4,%5,%6,%7}, {%8,%9}, {%0,%1,%2,%3};"
        : "+f"(c[0]), "+f"(c[1]), "+f"(c[2]), "+f"(c[3])
        : "r"(a[0]), "r"(a[1]), "r"(a[2]), "r"(a[3]), "r"(b0), "r"(b1));
}

// fp16: D(16x8) += A(16x16) * B(16x8)  (f32 accumulate)
__device__ __forceinline__ void mma_f16(float* c, const uint32_t* a, uint32_t b0, uint32_t b1) {
    asm volatile(
        "mma.sync.aligned.m16n8k16.row.col.f32.f16.f16.f32 "
        "{%0,%1,%2,%3}, {%4,%5,%6,%7}, {%8,%9}, {%0,%1,%2,%3};"
        : "+f"(c[0]), "+f"(c[1]), "+f"(c[2]), "+f"(c[3])
        : "r"(a[0]), "r"(a[1]), "r"(a[2]), "r"(a[3]), "r"(b0), "r"(b1));
}

__device__ __forceinline__ void ldsm_x4(uint32_t& r0, uint32_t& r1, uint32_t& r2, uint32_t& r3,
                                        uint32_t addr) {
    asm volatile("ldmatrix.sync.aligned.m8n8.x4.shared.b16 {%0,%1,%2,%3}, [%4];"
                 : "=r"(r0), "=r"(r1), "=r"(r2), "=r"(r3) : "r"(addr));
}

__device__ __forceinline__ void ldsm_x4_t(uint32_t& r0, uint32_t& r1, uint32_t& r2, uint32_t& r3,
                                          uint32_t addr) {
    asm volatile("ldmatrix.sync.aligned.m8n8.x4.trans.shared.b16 {%0,%1,%2,%3}, [%4];"
                 : "=r"(r0), "=r"(r1), "=r"(r2), "=r"(r3) : "r"(addr));
}

__device__ __forceinline__ uint32_t smem_u32(const void* p) {
    uint32_t a;
    asm("{ .reg .u64 t; cvta.to.shared.u64 t, %1; cvt.u32.u64 %0, t; }" : "=r"(a) : "l"(p));
    return a;
}

__device__ __forceinline__ void cp_async16(uint32_t dst, const void* src) {
    asm volatile("cp.async.cg.shared.global [%0], [%1], 16;" :: "r"(dst), "l"(src));
}
#define CP_COMMIT()  asm volatile("cp.async.commit_group;" ::: "memory")
#define CP_WAIT(N)   asm volatile("cp.async.wait_group %0;" :: "n"(N) : "memory")

__device__ __forceinline__ void bsplit(float x, __nv_bfloat16& h, __nv_bfloat16& l) {
    h = __float2bfloat16_rn(x);
    l = __float2bfloat16_rn(x - __bfloat162float(h));
}

__device__ __forceinline__ uint32_t packh(float a, float b) {
    __half2 t = __floats2half2_rn(a, b);
    return *(uint32_t*)&t;
}

// ==================== device scratch ====================
__device__ __nv_bfloat16 g_W1Th[NMID * E_DIM], g_W1Tl[NMID * E_DIM];
__device__ __nv_bfloat16 g_W2Th[E_DIM * E_DIM], g_W2Tl[E_DIM * E_DIM];
__device__ __nv_bfloat16 g_Ah[T_SEQ * E_DIM],  g_Al[T_SEQ * E_DIM];
__device__ __half g_Q[T_SEQ * 1024];   // q_lat * 0.125, fp16
__device__ __half g_K[T_SEQ * 64];     // latent_k, fp16
__device__ __half g_V[T_SEQ * 64];     // latent_v, fp16

// ---------------- split A: bf16 hi/lo decomposition ----------------
__global__ __launch_bounds__(256) void split_kernel(const float* __restrict__ src,
                                                    __nv_bfloat16* __restrict__ hi,
                                                    __nv_bfloat16* __restrict__ lo) {
    int i = (blockIdx.x * 256 + threadIdx.x) * 4;
    float4 v = *(const float4*)&src[i];
    __nv_bfloat16 h[4], l[4];
    bsplit(v.x, h[0], l[0]); bsplit(v.y, h[1], l[1]);
    bsplit(v.z, h[2], l[2]); bsplit(v.w, h[3], l[3]);
    *(__nv_bfloat162*)&hi[i]     = __nv_bfloat162{h[0], h[1]};
    *(__nv_bfloat162*)&hi[i + 2] = __nv_bfloat162{h[2], h[3]};
    *(__nv_bfloat162*)&lo[i]     = __nv_bfloat162{l[0], l[1]};
    *(__nv_bfloat162*)&lo[i + 2] = __nv_bfloat162{l[2], l[3]};
}

// ---------------- prep 1 ----------------
__global__ __launch_bounds__(256) void prep_w1_kernel(const float* __restrict__ Wq,
                                                      const float* __restrict__ q2l) {
    __shared__ float Wqs[64][65];
    __shared__ float Qls[64][65];
    const int h  = blockIdx.y;
    const int e0 = blockIdx.x * 64;
    const int tid = threadIdx.x, tx = tid & 15, ty = tid >> 4;

    #pragma unroll
    for (int i = 0; i < 16; i++) {
        int lin = tid + i * 256;
        int c = lin & 63, r = lin >> 6;
        Wqs[r][c] = Wq[(h * 64 + r) * E_DIM + e0 + c];
        Qls[r][c] = q2l[(h * 64 + r) * 64 + c];
    }
    __syncthreads();

    float acc[4][4];
    #pragma unroll
    for (int i = 0; i < 4; i++)
        #pragma unroll
        for (int j = 0; j < 4; j++) acc[i][j] = 0.f;

    #pragma unroll 8
    for (int d = 0; d < 64; d++) {
        float a[4], b[4];
        #pragma unroll
        for (int i = 0; i < 4; i++) a[i] = Wqs[d][ty * 4 + i];
        #pragma unroll
        for (int j = 0; j < 4; j++) b[j] = Qls[d][tx * 4 + j];
        #pragma unroll
        for (int i = 0; i < 4; i++)
            #pragma unroll
            for (int j = 0; j < 4; j++) acc[i][j] += a[i] * b[j];
    }
    #pragma unroll
    for (int j = 0; j < 4; j++)
        #pragma unroll
        for (int i = 0; i < 4; i++) {
            int idx = (h * 64 + tx * 4 + j) * E_DIM + e0 + ty * 4 + i;
            __nv_bfloat16 hf, lf; bsplit(acc[i][j], hf, lf);
            g_W1Th[idx] = hf; g_W1Tl[idx] = lf;
        }
}

// ---------------- prep 2 ----------------
__global__ __launch_bounds__(256) void prep_kv_kernel(const float* __restrict__ Wk,
                                                      const float* __restrict__ Wv) {
    int idx = blockIdx.x * 256 + threadIdx.x;   // 64 * 1024
    __nv_bfloat16 hf, lf;
    bsplit(Wk[idx], hf, lf);
    g_W1Th[1024 * E_DIM + idx] = hf; g_W1Tl[1024 * E_DIM + idx] = lf;
    bsplit(Wv[idx], hf, lf);
    g_W1Th[1088 * E_DIM + idx] = hf; g_W1Tl[1088 * E_DIM + idx] = lf;
}

// ---------------- prep 3 ----------------
__global__ __launch_bounds__(256) void prep_w2_kernel(const float* __restrict__ vup,
                                                      const float* __restrict__ Wout) {
    __shared__ __align__(16) float Wos[64][68];
    __shared__ __align__(16) float Vus[64][68];
    const int h  = blockIdx.y;
    const int e0 = blockIdx.x * 64;
    const int tid = threadIdx.x, tx = tid & 15, ty = tid >> 4;

    #pragma unroll
    for (int i = 0; i < 16; i++) {
        int lin = tid + i * 256;
        int c = lin & 63, r = lin >> 6;
        Wos[r][c] = Wout[(e0 + r) * E_DIM + h * 64 + c];
        Vus[r][c] = vup[(h * 64 + r) * 64 + c];
    }
    __syncthreads();

    float acc[4][4];
    #pragma unroll
    for (int i = 0; i < 4; i++)
        #pragma unroll
        for (int j = 0; j < 4; j++) acc[i][j] = 0.f;

    #pragma unroll
    for (int d4 = 0; d4 < 16; d4++) {
        float4 a[4], b[4];
        #pragma unroll
        for (int i = 0; i < 4; i++) a[i] = *(const float4*)&Vus[ty * 4 + i][d4 * 4];
        #pragma unroll
        for (int j = 0; j < 4; j++) b[j] = *(const float4*)&Wos[tx * 4 + j][d4 * 4];
        #pragma unroll
        for (int i = 0; i < 4; i++)
            #pragma unroll
            for (int j = 0; j < 4; j++)
                acc[i][j] += a[i].x * b[j].x + a[i].y * b[j].y +
                             a[i].z * b[j].z + a[i].w * b[j].w;
    }
    #pragma unroll
    for (int j = 0; j < 4; j++)
        #pragma unroll
        for (int i = 0; i < 4; i++) {
            int idx = (e0 + tx * 4 + j) * E_DIM + h * 64 + ty * 4 + i;
            __nv_bfloat16 hf, lf; bsplit(acc[i][j], hf, lf);
            g_W2Th[idx] = hf; g_W2Tl[idx] = lf;
        }
}

// ==================== bf16 3-term mma.sync GEMM (validated R8) ====================
#define ROWB 80
#define SA_H 0
#define SA_L (128 * ROWB)
#define SB_H (2 * 128 * ROWB)
#define SB_L (SB_H + 64 * ROWB)
#define SSZ  (SB_L + 64 * ROWB)
#define GEMM_SMEM (2 * SSZ)

__global__ __launch_bounds__(256, 2) void gemm_bf3(const __nv_bfloat16* __restrict__ Ah,
                                                   const __nv_bfloat16* __restrict__ Al,
                                                   const __nv_bfloat16* __restrict__ Bh,
                                                   const __nv_bfloat16* __restrict__ Bl,
                                                   float* __restrict__ C,
                                                   int N, int K, int mode) {
    extern __shared__ char gsm[];
    const uint32_t sbase = smem_u32(gsm);

    const int tid = threadIdx.x;
    const int wid = tid >> 5, lane = tid & 31;
    const int g = lane >> 2, tig = lane & 3;
    const int wm = wid & 3, wn = wid >> 2;
    const int m0 = blockIdx.y * 128;
    const int n0 = blockIdx.x * 64;
    const int nst = K >> 5;

    const uint32_t aRow = lane & 15;
    const uint32_t aSel = ((lane >> 4) & 1) * 16;
    const uint32_t bRow = (lane & 7) + ((lane & 16) ? 8 : 0);
    const uint32_t bSel = (lane & 8) ? 16 : 0;

    float c[2][4][4];
    #pragma unroll
    for (int mt = 0; mt < 2; mt++)
        #pragma unroll
        for (int nt = 0; nt < 4; nt++)
            #pragma unroll
            for (int j = 0; j < 4; j++) c[mt][nt][j] = 0.f;

    auto fetch = [&](int k0, int b) {
        const uint32_t s0 = sbase + (uint32_t)(b * SSZ);
        #pragma unroll
        for (int i = 0; i < 6; i++) {
            int idx = tid + i * 256;
            if (idx < 1024) {
                int t = idx >> 9;
                int r = (idx & 511) >> 2, cc = idx & 3;
                const __nv_bfloat16* src = (t ? Al : Ah) + (size_t)(m0 + r) * K + k0 + cc * 8;
                cp_async16(s0 + (t ? SA_L : SA_H) + r * ROWB + cc * 16, src);
            } else {
                int t = (idx - 1024) >> 8;
                int r = ((idx - 1024) & 255) >> 2, cc = idx & 3;
                const __nv_bfloat16* src = (t ? Bl : Bh) + (size_t)(n0 + r) * K + k0 + cc * 8;
                cp_async16(s0 + (t ? SB_L : SB_H) + r * ROWB + cc * 16, src);
            }
        }
        CP_COMMIT();
    };

    fetch(0, 0);

    for (int s = 0; s < nst; s++) {
        const int buf = s & 1;
        if (s + 1 < nst) { fetch((s + 1) << 5, buf ^ 1); CP_WAIT(1); }
        else             { CP_WAIT(0); }
        __syncthreads();

        const uint32_t sb = sbase + (uint32_t)(buf * SSZ);
        #pragma unroll
        for (int ks = 0; ks < 2; ks++) {
            uint32_t ah[2][4], al[2][4];
            #pragma unroll
            for (int mt = 0; mt < 2; mt++) {
                uint32_t ra = (wm * 32 + mt * 16 + aRow) * ROWB + ks * 32 + aSel;
                ldsm_x4(ah[mt][0], ah[mt][1], ah[mt][2], ah[mt][3], sb + SA_H + ra);
                ldsm_x4(al[mt][0], al[mt][1], al[mt][2], al[mt][3], sb + SA_L + ra);
            }
            #pragma unroll
            for (int ntp = 0; ntp < 2; ntp++) {
                uint32_t rb = (wn * 32 + ntp * 16 + bRow) * ROWB + ks * 32 + bSel;
                uint32_t h0, h1, h2, h3, l0, l1, l2, l3;
                ldsm_x4(h0, h1, h2, h3, sb + SB_H + rb);
                ldsm_x4(l0, l1, l2, l3, sb + SB_L + rb);
                #pragma unroll
                for (int mt = 0; mt < 2; mt++) {
                    float* c0 = c[mt][2 * ntp];
                    float* c1 = c[mt][2 * ntp + 1];
                    mma_bf16(c0, ah[mt], h0, h1);
                    mma_bf16(c0, ah[mt], l0, l1);
                    mma_bf16(c0, al[mt], h0, h1);
                    mma_bf16(c1, ah[mt], h2, h3);
                    mma_bf16(c1, ah[mt], l2, l3);
                    mma_bf16(c1, al[mt], h2, h3);
                }
            }
        }
        __syncthreads();
    }

    // epilogue.  mode 1 = GEMM1: q_lat -> g_Q fp16 (x0.125), K -> g_K fp16, V -> g_V fp16
    #pragma unroll
    for (int mt = 0; mt < 2; mt++) {
        int row0 = m0 + wm * 32 + mt * 16 + g;
        #pragma unroll
        for (int nt = 0; nt < 4; nt++) {
            int col = n0 + wn * 32 + nt * 8 + 2 * tig;
            float v0 = c[mt][nt][0], v1 = c[mt][nt][1];
            float v2 = c[mt][nt][2], v3 = c[mt][nt][3];
            if (mode == 1) {
                if (col < 1024) {
                    *(uint32_t*)&g_Q[(size_t)row0 * 1024 + col] =
                        packh(v0 * 0.125f, v1 * 0.125f);
                    *(uint32_t*)&g_Q[(size_t)(row0 + 8) * 1024 + col] =
                        packh(v2 * 0.125f, v3 * 0.125f);
                } else if (col < 1088) {
                    int kc = col - 1024;
                    *(uint32_t*)&g_K[(size_t)row0 * 64 + kc]       = packh(v0, v1);
                    *(uint32_t*)&g_K[(size_t)(row0 + 8) * 64 + kc] = packh(v2, v3);
                } else {
                    int vc = col - 1088;
                    *(uint32_t*)&g_V[(size_t)row0 * 64 + vc]       = packh(v0, v1);
                    *(uint32_t*)&g_V[(size_t)(row0 + 8) * 64 + vc] = packh(v2, v3);
                }
            } else {
                *(float2*)&C[(size_t)row0 * N + col]       = make_float2(v0, v1);
                *(float2*)&C[(size_t)(row0 + 8) * N + col] = make_float2(v2, v3);
            }
        }
    }
}

// ==================== fp16 flash attention, 64-row q tiles (load-balanced) ===========
// CTA: 64-query tile, 4 warps x 16 rows, KV tiles 64.  Epilogue -> bf16 hi/lo ctx.
#define AROW 144                       // padded row bytes (64 fp16 = 128B data)
#define AQ_B 0
#define AKV_B (64 * AROW)              // 9216
#define AST_B (2 * 64 * AROW)          // stage: K + V
#define AV_B  (64 * AROW)
#define ATTN_SMEM (AKV_B + 2 * AST_B)  // 46080

__global__ __launch_bounds__(128, 4) void attn_mma() {
    extern __shared__ char asm_[];
    const uint32_t sbase = smem_u32(asm_);
    const int tid = threadIdx.x;
    const int wid = tid >> 5, lane = tid & 31;
    const int g = lane >> 2, tig = lane & 3;
    const int wq = wid * 16;
    const int qt = (int)gridDim.x - 1 - (int)blockIdx.x;  // heavy first
    const int h  = blockIdx.y;
    const int q0 = qt * 64;
    const int nkv = qt + 1;

    const uint32_t aRow = lane & 15;
    const uint32_t aSel = ((lane >> 4) & 1) * 16;
    const uint32_t bRow = (lane & 7) + ((lane & 16) ? 8 : 0);
    const uint32_t bSel = (lane & 8) ? 16 : 0;
    const int vrow = lane & 7;
    const int vmk  = (lane >> 3) & 1;
    const int vmn  = (lane >> 4) & 1;

    auto fetch_kv = [&](int blk, int b) {
        const uint32_t st = sbase + (uint32_t)(AKV_B + b * AST_B);
        #pragma unroll
        for (int i = 0; i < 8; i++) {     // 1024 chunks: K 512 + V 512
            int idx = tid + i * 128;
            int isV = idx >> 9;
            int r = (idx & 511) >> 3, cc = idx & 7;
            const __half* src = (isV ? g_V : g_K) + (size_t)(blk * 64 + r) * 64 + cc * 8;
            cp_async16(st + (isV ? AV_B : 0) + r * AROW + cc * 16, src);
        }
        CP_COMMIT();
    };

    // prologue: KV block 0 + Q tile
    fetch_kv(0, 0);
    {
        #pragma unroll
        for (int i = 0; i < 4; i++) {     // 512 chunks
            int idx = tid + i * 128;
            int r = idx >> 3, cc = idx & 7;
            cp_async16(sbase + (uint32_t)(AQ_B + r * AROW + cc * 16),
                       &g_Q[(size_t)(q0 + r) * 1024 + h * 64 + cc * 8]);
        }
        CP_COMMIT();
    }
    CP_WAIT(0);
    __syncthreads();

    // preload Q A-fragments: 4 k-steps (k16 each)
    uint32_t qa[4][4];
    #pragma unroll
    for (int ks = 0; ks < 4; ks++) {
        uint32_t ra = sbase + (uint32_t)(AQ_B + (wq + aRow) * AROW + ks * 32) + aSel;
        ldsm_x4(qa[ks][0], qa[ks][1], qa[ks][2], qa[ks][3], ra);
    }

    float o[8][4];
    #pragma unroll
    for (int nt = 0; nt < 8; nt++)
        #pragma unroll
        for (int j = 0; j < 4; j++) o[nt][j] = 0.f;
    float m0r = -1e30f, m1r = -1e30f, l0r = 0.f, l1r = 0.f;

    for (int kb = 0; kb < nkv; kb++) {
        const int buf = kb & 1;
        if (kb + 1 < nkv) { fetch_kv(kb + 1, buf ^ 1); CP_WAIT(1); }
        else              { CP_WAIT(0); }
        __syncthreads();

        const uint32_t stb = sbase + (uint32_t)(AKV_B + buf * AST_B);
        const int s0 = kb * 64;

        // S = Q @ K^T
        float s[8][4];
        #pragma unroll
        for (int nt = 0; nt < 8; nt++)
            s[nt][0] = s[nt][1] = s[nt][2] = s[nt][3] = 0.f;
        #pragma unroll
        for (int ntp = 0; ntp < 4; ntp++) {
            #pragma unroll
            for (int ks = 0; ks < 4; ks++) {
                uint32_t addr = stb + (uint32_t)((ntp * 16 + bRow) * AROW + ks * 32) + bSel;
                uint32_t k0, k1, k2, k3;
                ldsm_x4(k0, k1, k2, k3, addr);
                mma_f16(s[2 * ntp],     qa[ks], k0, k1);
                mma_f16(s[2 * ntp + 1], qa[ks], k2, k3);
            }
        }

        // causal mask (only the diagonal tile)
        if (kb == qt) {
            int row0 = q0 + wq + g, row1 = row0 + 8;
            #pragma unroll
            for (int nt = 0; nt < 8; nt++) {
                int c0 = s0 + nt * 8 + 2 * tig;
                if (c0     > row0) s[nt][0] = -1e30f;
                if (c0 + 1 > row0) s[nt][1] = -1e30f;
                if (c0     > row1) s[nt][2] = -1e30f;
                if (c0 + 1 > row1) s[nt][3] = -1e30f;
            }
        }

        // online softmax
        float rm0 = -1e30f, rm1 = -1e30f;
        #pragma unroll
        for (int nt = 0; nt < 8; nt++) {
            rm0 = fmaxf(rm0, fmaxf(s[nt][0], s[nt][1]));
            rm1 = fmaxf(rm1, fmaxf(s[nt][2], s[nt][3]));
        }
        rm0 = fmaxf(rm0, __shfl_xor_sync(0xffffffffu, rm0, 1));
        rm0 = fmaxf(rm0, __shfl_xor_sync(0xffffffffu, rm0, 2));
        rm1 = fmaxf(rm1, __shfl_xor_sync(0xffffffffu, rm1, 1));
        rm1 = fmaxf(rm1, __shfl_xor_sync(0xffffffffu, rm1, 2));
        float mn0 = fmaxf(m0r, rm0), mn1 = fmaxf(m1r, rm1);
        float al0 = __expf(m0r - mn0), al1 = __expf(m1r - mn1);
        m0r = mn0; m1r = mn1;

        float rs0 = 0.f, rs1 = 0.f;
        #pragma unroll
        for (int nt = 0; nt < 8; nt++) {
            s[nt][0] = __expf(s[nt][0] - mn0); rs0 += s[nt][0];
            s[nt][1] = __expf(s[nt][1] - mn0); rs0 += s[nt][1];
            s[nt][2] = __expf(s[nt][2] - mn1); rs1 += s[nt][2];
            s[nt][3] = __expf(s[nt][3] - mn1); rs1 += s[nt][3];
        }
        rs0 += __shfl_xor_sync(0xffffffffu, rs0, 1);
        rs0 += __shfl_xor_sync(0xffffffffu, rs0, 2);
        rs1 += __shfl_xor_sync(0xffffffffu, rs1, 1);
        rs1 += __shfl_xor_sync(0xffffffffu, rs1, 2);
        l0r = l0r * al0 + rs0;
        l1r = l1r * al1 + rs1;

        // O = O*alpha + P @ V
        #pragma unroll
        for (int nt = 0; nt < 8; nt++) {
            o[nt][0] *= al0; o[nt][1] *= al0;
            o[nt][2] *= al1; o[nt][3] *= al1;
        }
        #pragma unroll
        for (int ks = 0; ks < 4; ks++) {
            uint32_t pa[4];
            pa[0] = packh(s[2 * ks][0],     s[2 * ks][1]);
            pa[1] = packh(s[2 * ks][2],     s[2 * ks][3]);
            pa[2] = packh(s[2 * ks + 1][0], s[2 * ks + 1][1]);
            pa[3] = packh(s[2 * ks + 1][2], s[2 * ks + 1][3]);
            #pragma unroll
            for (int ntp = 0; ntp < 4; ntp++) {
                uint32_t rowk = ks * 16 + vmk * 8 + vrow;
                uint32_t coln = ntp * 16 + vmn * 8;
                uint32_t va = stb + AV_B + rowk * AROW + coln * 2;
                uint32_t v0, v1, v2, v3;
                ldsm_x4_t(v0, v1, v2, v3, va);
                mma_f16(o[2 * ntp],     pa, v0, v1);
                mma_f16(o[2 * ntp + 1], pa, v2, v3);
            }
        }
        __syncthreads();
    }

    // normalize + write ctx as bf16 hi/lo (feeds GEMM2 directly; no split pass)
    float inv0 = 1.0f / l0r, inv1 = 1.0f / l1r;
    int row0 = q0 + wq + g;
    #pragma unroll
    for (int nt = 0; nt < 8; nt++) {
        int col = h * 64 + nt * 8 + 2 * tig;
        float v0 = o[nt][0] * inv0, v1 = o[nt][1] * inv0;
        float v2 = o[nt][2] * inv1, v3 = o[nt][3] * inv1;
        __nv_bfloat16 h0, l0, h1, l1;
        bsplit(v0, h0, l0); bsplit(v1, h1, l1);
        *(__nv_bfloat162*)&g_Ah[(size_t)row0 * E_DIM + col] = __nv_bfloat162{h0, h1};
        *(__nv_bfloat162*)&g_Al[(size_t)row0 * E_DIM + col] = __nv_bfloat162{l0, l1};
        bsplit(v2, h0, l0); bsplit(v3, h1, l1);
        *(__nv_bfloat162*)&g_Ah[(size_t)(row0 + 8) * E_DIM + col] = __nv_bfloat162{h0, h1};
        *(__nv_bfloat162*)&g_Al[(size_t)(row0 + 8) * E_DIM + col] = __nv_bfloat162{l0, l1};
    }
}

// ---------------- launch ----------------
extern "C" void kernel_launch(void* const* d_in, const int* in_sizes, int n_in,
                              void* d_out, int out_size) {
    const float* hidden = (const float*)d_in[0];
    const float* Wq     = (const float*)d_in[1];
    const float* Wk     = (const float*)d_in[2];
    const float* Wv     = (const float*)d_in[3];
    const float* q2l    = (const float*)d_in[4];
    const float* vup    = (const float*)d_in[5];
    const float* Wout   = (const float*)d_in[6];
    float* out = (float*)d_out;

    void *w1h, *w1l, *w2h, *w2l, *ah, *al;
    cudaGetSymbolAddress(&w1h, g_W1Th); cudaGetSymbolAddress(&w1l, g_W1Tl);
    cudaGetSymbolAddress(&w2h, g_W2Th); cudaGetSymbolAddress(&w2l, g_W2Tl);
    cudaGetSymbolAddress(&ah,  g_Ah);   cudaGetSymbolAddress(&al,  g_Al);

    cudaFuncSetAttribute(gemm_bf3, cudaFuncAttributeMaxDynamicSharedMemorySize, GEMM_SMEM);
    cudaFuncSetAttribute(attn_mma, cudaFuncAttributeMaxDynamicSharedMemorySize, ATTN_SMEM);

    prep_w1_kernel<<<dim3(16, 16), 256>>>(Wq, q2l);
    prep_kv_kernel<<<256, 256>>>(Wk, Wv);
    prep_w2_kernel<<<dim3(16, 16), 256>>>(vup, Wout);

    split_kernel<<<T_SEQ * E_DIM / 1024, 256>>>(hidden, (__nv_bfloat16*)ah, (__nv_bfloat16*)al);

    // GEMM1: epilogue emits fp16 Q/K/V directly (mode 1)
    gemm_bf3<<<dim3(NMID / 64, T_SEQ / 128), 256, GEMM_SMEM>>>(
        (const __nv_bfloat16*)ah, (const __nv_bfloat16*)al,
        (const __nv_bfloat16*)w1h, (const __nv_bfloat16*)w1l,
        out /*unused in mode 1*/, NMID, E_DIM, 1);

    // attention: 64-row q tiles, writes bf16 hi/lo ctx into g_Ah/g_Al
    attn_mma<<<dim3(T_SEQ / 64, H_NUM), 128, ATTN_SMEM>>>();

    // GEMM2 consumes g_Ah/g_Al directly
    gemm_bf3<<<dim3(E_DIM / 64, T_SEQ / 128), 256, GEMM_SMEM>>>(
        (const __nv_bfloat16*)ah, (const __nv_bfloat16*)al,
        (const __nv_bfloat16*)w2h, (const __nv_bfloat16*)w2l,
        out, E_DIM, E_DIM, 0);
}

// round 12
// speedup vs baseline: 1.4013x; 1.0067x over previous
#include <cuda_runtime.h>
#include <cuda_bf16.h>
#include <cuda_fp16.h>
#include <cstdint>

#define T_SEQ 2048
#define E_DIM 1024
#define H_NUM 16
#define L_DIM 64
#define NMID  1152   // 1024 q_lat cols + 64 latent_k + 64 latent_v

// ==================== helpers ====================
// bf16: D(16x8) += A(16x16) * B(16x8)
__device__ __forceinline__ void mma_bf16(float* c, const uint32_t* a, uint32_t b0, uint32_t b1) {
    asm volatile(
        "mma.sync.aligned.m16n8k16.row.col.f32.bf16.bf16.f32 "
        "{%0,%1,%2,%3}, {%4,%5,%6,%7}, {%8,%9}, {%0,%1,%2,%3};"
        : "+f"(c[0]), "+f"(c[1]), "+f"(c[2]), "+f"(c[3])
        : "r"(a[0]), "r"(a[1]), "r"(a[2]), "r"(a[3]), "r"(b0), "r"(b1));
}

// fp16: D(16x8) += A(16x16) * B(16x8)  (f32 accumulate)
__device__ __forceinline__ void mma_f16(float* c, const uint32_t* a, uint32_t b0, uint32_t b1) {
    asm volatile(
        "mma.sync.aligned.m16n8k16.row.col.f32.f16.f16.f32 "
        "{%0,%1,%2,%3}, {%4,%5,%6,%7}, {%8,%9}, {%0,%1,%2,%3};"
        : "+f"(c[0]), "+f"(c[1]), "+f"(c[2]), "+f"(c[3])
        : "r"(a[0]), "r"(a[1]), "r"(a[2]), "r"(a[3]), "r"(b0), "r"(b1));
}

__device__ __forceinline__ void ldsm_x4(uint32_t& r0, uint32_t& r1, uint32_t& r2, uint32_t& r3,
                                        uint32_t addr) {
    asm volatile("ldmatrix.sync.aligned.m8n8.x4.shared.b16 {%0,%1,%2,%3}, [%4];"
                 : "=r"(r0), "=r"(r1), "=r"(r2), "=r"(r3) : "r"(addr));
}

__device__ __forceinline__ void ldsm_x4_t(uint32_t& r0, uint32_t& r1, uint32_t& r2, uint32_t& r3,
                                          uint32_t addr) {
    asm volatile("ldmatrix.sync.aligned.m8n8.x4.trans.shared.b16 {%0,%1,%2,%3}, [%4];"
                 : "=r"(r0), "=r"(r1), "=r"(r2), "=r"(r3) : "r"(addr));
}

__device__ __forceinline__ uint32_t smem_u32(const void* p) {
    uint32_t a;
    asm("{ .reg .u64 t; cvta.to.shared.u64 t, %1; cvt.u32.u64 %0, t; }" : "=r"(a) : "l"(p));
    return a;
}

__device__ __forceinline__ void cp_async16(uint32_t dst, const void* src) {
    asm volatile("cp.async.cg.shared.global [%0], [%1], 16;" :: "r"(dst), "l"(src));
}
#define CP_COMMIT()  asm volatile("cp.async.commit_group;" ::: "memory")
#define CP_WAIT(N)   asm volatile("cp.async.wait_group %0;" :: "n"(N) : "memory")

__device__ __forceinline__ void bsplit(float x, __nv_bfloat16& h, __nv_bfloat16& l) {
    h = __float2bfloat16_rn(x);
    l = __float2bfloat16_rn(x - __bfloat162float(h));
}

__device__ __forceinline__ uint32_t packh(float a, float b) {
    __half2 t = __floats2half2_rn(a, b);
    return *(uint32_t*)&t;
}

// ==================== device scratch ====================
__device__ __nv_bfloat16 g_W1Th[NMID * E_DIM], g_W1Tl[NMID * E_DIM];
__device__ __nv_bfloat16 g_W2Th[E_DIM * E_DIM], g_W2Tl[E_DIM * E_DIM];
__device__ __nv_bfloat16 g_Ah[T_SEQ * E_DIM],  g_Al[T_SEQ * E_DIM];
__device__ __half g_Q[T_SEQ * 1024];   // q_lat * 0.125, fp16
__device__ __half g_K[T_SEQ * 64];     // latent_k, fp16
__device__ __half g_V[T_SEQ * 64];     // latent_v, fp16

// ---------------- split A: bf16 hi/lo decomposition ----------------
__global__ __launch_bounds__(256) void split_kernel(const float* __restrict__ src,
                                                    __nv_bfloat16* __restrict__ hi,
                                                    __nv_bfloat16* __restrict__ lo) {
    int i = (blockIdx.x * 256 + threadIdx.x) * 4;
    float4 v = *(const float4*)&src[i];
    __nv_bfloat16 h[4], l[4];
    bsplit(v.x, h[0], l[0]); bsplit(v.y, h[1], l[1]);
    bsplit(v.z, h[2], l[2]); bsplit(v.w, h[3], l[3]);
    *(__nv_bfloat162*)&hi[i]     = __nv_bfloat162{h[0], h[1]};
    *(__nv_bfloat162*)&hi[i + 2] = __nv_bfloat162{h[2], h[3]};
    *(__nv_bfloat162*)&lo[i]     = __nv_bfloat162{l[0], l[1]};
    *(__nv_bfloat162*)&lo[i + 2] = __nv_bfloat162{l[2], l[3]};
}

// ---------------- prep 1 ----------------
__global__ __launch_bounds__(256) void prep_w1_kernel(const float* __restrict__ Wq,
                                                      const float* __restrict__ q2l) {
    __shared__ float Wqs[64][65];
    __shared__ float Qls[64][65];
    const int h  = blockIdx.y;
    const int e0 = blockIdx.x * 64;
    const int tid = threadIdx.x, tx = tid & 15, ty = tid >> 4;

    #pragma unroll
    for (int i = 0; i < 16; i++) {
        int lin = tid + i * 256;
        int c = lin & 63, r = lin >> 6;
        Wqs[r][c] = Wq[(h * 64 + r) * E_DIM + e0 + c];
        Qls[r][c] = q2l[(h * 64 + r) * 64 + c];
    }
    __syncthreads();

    float acc[4][4];
    #pragma unroll
    for (int i = 0; i < 4; i++)
        #pragma unroll
        for (int j = 0; j < 4; j++) acc[i][j] = 0.f;

    #pragma unroll 8
    for (int d = 0; d < 64; d++) {
        float a[4], b[4];
        #pragma unroll
        for (int i = 0; i < 4; i++) a[i] = Wqs[d][ty * 4 + i];
        #pragma unroll
        for (int j = 0; j < 4; j++) b[j] = Qls[d][tx * 4 + j];
        #pragma unroll
        for (int i = 0; i < 4; i++)
            #pragma unroll
            for (int j = 0; j < 4; j++) acc[i][j] += a[i] * b[j];
    }
    #pragma unroll
    for (int j = 0; j < 4; j++)
        #pragma unroll
        for (int i = 0; i < 4; i++) {
            int idx = (h * 64 + tx * 4 + j) * E_DIM + e0 + ty * 4 + i;
            __nv_bfloat16 hf, lf; bsplit(acc[i][j], hf, lf);
            g_W1Th[idx] = hf; g_W1Tl[idx] = lf;
        }
}

// ---------------- prep 2 ----------------
__global__ __launch_bounds__(256) void prep_kv_kernel(const float* __restrict__ Wk,
                                                      const float* __restrict__ Wv) {
    int idx = blockIdx.x * 256 + threadIdx.x;   // 64 * 1024
    __nv_bfloat16 hf, lf;
    bsplit(Wk[idx], hf, lf);
    g_W1Th[1024 * E_DIM + idx] = hf; g_W1Tl[1024 * E_DIM + idx] = lf;
    bsplit(Wv[idx], hf, lf);
    g_W1Th[1088 * E_DIM + idx] = hf; g_W1Tl[1088 * E_DIM + idx] = lf;
}

// ---------------- prep 3 ----------------
__global__ __launch_bounds__(256) void prep_w2_kernel(const float* __restrict__ vup,
                                                      const float* __restrict__ Wout) {
    __shared__ __align__(16) float Wos[64][68];
    __shared__ __align__(16) float Vus[64][68];
    const int h  = blockIdx.y;
    const int e0 = blockIdx.x * 64;
    const int tid = threadIdx.x, tx = tid & 15, ty = tid >> 4;

    #pragma unroll
    for (int i = 0; i < 16; i++) {
        int lin = tid + i * 256;
        int c = lin & 63, r = lin >> 6;
        Wos[r][c] = Wout[(e0 + r) * E_DIM + h * 64 + c];
        Vus[r][c] = vup[(h * 64 + r) * 64 + c];
    }
    __syncthreads();

    float acc[4][4];
    #pragma unroll
    for (int i = 0; i < 4; i++)
        #pragma unroll
        for (int j = 0; j < 4; j++) acc[i][j] = 0.f;

    #pragma unroll
    for (int d4 = 0; d4 < 16; d4++) {
        float4 a[4], b[4];
        #pragma unroll
        for (int i = 0; i < 4; i++) a[i] = *(const float4*)&Vus[ty * 4 + i][d4 * 4];
        #pragma unroll
        for (int j = 0; j < 4; j++) b[j] = *(const float4*)&Wos[tx * 4 + j][d4 * 4];
        #pragma unroll
        for (int i = 0; i < 4; i++)
            #pragma unroll
            for (int j = 0; j < 4; j++)
                acc[i][j] += a[i].x * b[j].x + a[i].y * b[j].y +
                             a[i].z * b[j].z + a[i].w * b[j].w;
    }
    #pragma unroll
    for (int j = 0; j < 4; j++)
        #pragma unroll
        for (int i = 0; i < 4; i++) {
            int idx = (e0 + tx * 4 + j) * E_DIM + h * 64 + ty * 4 + i;
            __nv_bfloat16 hf, lf; bsplit(acc[i][j], hf, lf);
            g_W2Th[idx] = hf; g_W2Tl[idx] = lf;
        }
}

// ==================== bf16 3-term mma.sync GEMM, 3-stage ring, 1 sync/stage =========
#define ROWB 80
#define SA_H 0
#define SA_L (128 * ROWB)
#define SB_H (2 * 128 * ROWB)
#define SB_L (SB_H + 64 * ROWB)
#define SSZ  (SB_L + 64 * ROWB)        // 30720 B per stage
#define GEMM_SMEM (3 * SSZ)            // 92160 B

__global__ __launch_bounds__(256, 2) void gemm_bf3(const __nv_bfloat16* __restrict__ Ah,
                                                   const __nv_bfloat16* __restrict__ Al,
                                                   const __nv_bfloat16* __restrict__ Bh,
                                                   const __nv_bfloat16* __restrict__ Bl,
                                                   float* __restrict__ C,
                                                   int N, int K, int mode) {
    extern __shared__ char gsm[];
    const uint32_t sbase = smem_u32(gsm);

    const int tid = threadIdx.x;
    const int wid = tid >> 5, lane = tid & 31;
    const int g = lane >> 2, tig = lane & 3;
    const int wm = wid & 3, wn = wid >> 2;
    const int m0 = blockIdx.y * 128;
    const int n0 = blockIdx.x * 64;
    const int nst = K >> 5;

    const uint32_t aRow = lane & 15;
    const uint32_t aSel = ((lane >> 4) & 1) * 16;
    const uint32_t bRow = (lane & 7) + ((lane & 16) ? 8 : 0);
    const uint32_t bSel = (lane & 8) ? 16 : 0;

    float c[2][4][4];
    #pragma unroll
    for (int mt = 0; mt < 2; mt++)
        #pragma unroll
        for (int nt = 0; nt < 4; nt++)
            #pragma unroll
            for (int j = 0; j < 4; j++) c[mt][nt][j] = 0.f;

    auto fetch = [&](int k0, int b) {
        const uint32_t s0 = sbase + (uint32_t)(b * SSZ);
        #pragma unroll
        for (int i = 0; i < 6; i++) {
            int idx = tid + i * 256;
            if (idx < 1024) {
                int t = idx >> 9;
                int r = (idx & 511) >> 2, cc = idx & 3;
                const __nv_bfloat16* src = (t ? Al : Ah) + (size_t)(m0 + r) * K + k0 + cc * 8;
                cp_async16(s0 + (t ? SA_L : SA_H) + r * ROWB + cc * 16, src);
            } else {
                int t = (idx - 1024) >> 8;
                int r = ((idx - 1024) & 255) >> 2, cc = idx & 3;
                const __nv_bfloat16* src = (t ? Bl : Bh) + (size_t)(n0 + r) * K + k0 + cc * 8;
                cp_async16(s0 + (t ? SB_L : SB_H) + r * ROWB + cc * 16, src);
            }
        }
        CP_COMMIT();
    };

    // prologue: 2 stages in flight
    fetch(0, 0);
    fetch(32, 1);

    for (int s = 0; s < nst; s++) {
        const int buf = s - (s / 3) * 3;          // s % 3
        if (s + 1 < nst) CP_WAIT(1);              // stage s landed (s+1 may fly)
        else             CP_WAIT(0);
        __syncthreads();                          // data ready + buffer (s+2)%3 free
        if (s + 2 < nst) {
            int nb = (s + 2) - ((s + 2) / 3) * 3;
            fetch((s + 2) << 5, nb);
        }

        const uint32_t sb = sbase + (uint32_t)(buf * SSZ);
        #pragma unroll
        for (int ks = 0; ks < 2; ks++) {
            uint32_t ah[2][4], al[2][4];
            #pragma unroll
            for (int mt = 0; mt < 2; mt++) {
                uint32_t ra = (wm * 32 + mt * 16 + aRow) * ROWB + ks * 32 + aSel;
                ldsm_x4(ah[mt][0], ah[mt][1], ah[mt][2], ah[mt][3], sb + SA_H + ra);
                ldsm_x4(al[mt][0], al[mt][1], al[mt][2], al[mt][3], sb + SA_L + ra);
            }
            #pragma unroll
            for (int ntp = 0; ntp < 2; ntp++) {
                uint32_t rb = (wn * 32 + ntp * 16 + bRow) * ROWB + ks * 32 + bSel;
                uint32_t h0, h1, h2, h3, l0, l1, l2, l3;
                ldsm_x4(h0, h1, h2, h3, sb + SB_H + rb);
                ldsm_x4(l0, l1, l2, l3, sb + SB_L + rb);
                #pragma unroll
                for (int mt = 0; mt < 2; mt++) {
                    float* c0 = c[mt][2 * ntp];
                    float* c1 = c[mt][2 * ntp + 1];
                    mma_bf16(c0, ah[mt], h0, h1);
                    mma_bf16(c0, ah[mt], l0, l1);
                    mma_bf16(c0, al[mt], h0, h1);
                    mma_bf16(c1, ah[mt], h2, h3);
                    mma_bf16(c1, ah[mt], l2, l3);
                    mma_bf16(c1, al[mt], h2, h3);
                }
            }
        }
        // no tail sync: next iteration's barrier covers the WAR on buffer reuse
    }

    // epilogue.  mode 1 = GEMM1: q_lat -> g_Q fp16 (x0.125), K -> g_K fp16, V -> g_V fp16
    #pragma unroll
    for (int mt = 0; mt < 2; mt++) {
        int row0 = m0 + wm * 32 + mt * 16 + g;
        #pragma unroll
        for (int nt = 0; nt < 4; nt++) {
            int col = n0 + wn * 32 + nt * 8 + 2 * tig;
            float v0 = c[mt][nt][0], v1 = c[mt][nt][1];
            float v2 = c[mt][nt][2], v3 = c[mt][nt][3];
            if (mode == 1) {
                if (col < 1024) {
                    *(uint32_t*)&g_Q[(size_t)row0 * 1024 + col] =
                        packh(v0 * 0.125f, v1 * 0.125f);
                    *(uint32_t*)&g_Q[(size_t)(row0 + 8) * 1024 + col] =
                        packh(v2 * 0.125f, v3 * 0.125f);
                } else if (col < 1088) {
                    int kc = col - 1024;
                    *(uint32_t*)&g_K[(size_t)row0 * 64 + kc]       = packh(v0, v1);
                    *(uint32_t*)&g_K[(size_t)(row0 + 8) * 64 + kc] = packh(v2, v3);
                } else {
                    int vc = col - 1088;
                    *(uint32_t*)&g_V[(size_t)row0 * 64 + vc]       = packh(v0, v1);
                    *(uint32_t*)&g_V[(size_t)(row0 + 8) * 64 + vc] = packh(v2, v3);
                }
            } else {
                *(float2*)&C[(size_t)row0 * N + col]       = make_float2(v0, v1);
                *(float2*)&C[(size_t)(row0 + 8) * N + col] = make_float2(v2, v3);
            }
        }
    }
}

// ==================== fp16 flash attention, 64-row q tiles, 1 sync/tile =============
#define AROW 144
#define AQ_B 0
#define AKV_B (64 * AROW)              // 9216
#define AST_B (2 * 64 * AROW)
#define AV_B  (64 * AROW)
#define ATTN_SMEM (AKV_B + 2 * AST_B)  // 46080

__global__ __launch_bounds__(128, 4) void attn_mma() {
    extern __shared__ char asm_[];
    const uint32_t sbase = smem_u32(asm_);
    const int tid = threadIdx.x;
    const int wid = tid >> 5, lane = tid & 31;
    const int g = lane >> 2, tig = lane & 3;
    const int wq = wid * 16;
    const int qt = (int)gridDim.x - 1 - (int)blockIdx.x;  // heavy first
    const int h  = blockIdx.y;
    const int q0 = qt * 64;
    const int nkv = qt + 1;

    const uint32_t aRow = lane & 15;
    const uint32_t aSel = ((lane >> 4) & 1) * 16;
    const uint32_t bRow = (lane & 7) + ((lane & 16) ? 8 : 0);
    const uint32_t bSel = (lane & 8) ? 16 : 0;
    const int vrow = lane & 7;
    const int vmk  = (lane >> 3) & 1;
    const int vmn  = (lane >> 4) & 1;

    auto fetch_kv = [&](int blk, int b) {
        const uint32_t st = sbase + (uint32_t)(AKV_B + b * AST_B);
        #pragma unroll
        for (int i = 0; i < 8; i++) {
            int idx = tid + i * 128;
            int isV = idx >> 9;
            int r = (idx & 511) >> 3, cc = idx & 7;
            const __half* src = (isV ? g_V : g_K) + (size_t)(blk * 64 + r) * 64 + cc * 8;
            cp_async16(st + (isV ? AV_B : 0) + r * AROW + cc * 16, src);
        }
        CP_COMMIT();
    };

    // prologue: KV block 0 + Q tile
    fetch_kv(0, 0);
    {
        #pragma unroll
        for (int i = 0; i < 4; i++) {
            int idx = tid + i * 128;
            int r = idx >> 3, cc = idx & 7;
            cp_async16(sbase + (uint32_t)(AQ_B + r * AROW + cc * 16),
                       &g_Q[(size_t)(q0 + r) * 1024 + h * 64 + cc * 8]);
        }
        CP_COMMIT();
    }
    CP_WAIT(0);
    __syncthreads();

    // preload Q A-fragments
    uint32_t qa[4][4];
    #pragma unroll
    for (int ks = 0; ks < 4; ks++) {
        uint32_t ra = sbase + (uint32_t)(AQ_B + (wq + aRow) * AROW + ks * 32) + aSel;
        ldsm_x4(qa[ks][0], qa[ks][1], qa[ks][2], qa[ks][3], ra);
    }

    float o[8][4];
    #pragma unroll
    for (int nt = 0; nt < 8; nt++)
        #pragma unroll
        for (int j = 0; j < 4; j++) o[nt][j] = 0.f;
    float m0r = -1e30f, m1r = -1e30f, l0r = 0.f, l1r = 0.f;

    for (int kb = 0; kb < nkv; kb++) {
        const int buf = kb & 1;
        if (kb > 0) {
            CP_WAIT(0);          // fetch(kb) landed
            __syncthreads();     // + everyone done with buf (read in compute(kb-1))
        }
        if (kb + 1 < nkv) fetch_kv(kb + 1, buf ^ 1);

        const uint32_t stb = sbase + (uint32_t)(AKV_B + buf * AST_B);
        const int s0 = kb * 64;

        // S = Q @ K^T
        float s[8][4];
        #pragma unroll
        for (int nt = 0; nt < 8; nt++)
            s[nt][0] = s[nt][1] = s[nt][2] = s[nt][3] = 0.f;
        #pragma unroll
        for (int ntp = 0; ntp < 4; ntp++) {
            #pragma unroll
            for (int ks = 0; ks < 4; ks++) {
                uint32_t addr = stb + (uint32_t)((ntp * 16 + bRow) * AROW + ks * 32) + bSel;
                uint32_t k0, k1, k2, k3;
                ldsm_x4(k0, k1, k2, k3, addr);
                mma_f16(s[2 * ntp],     qa[ks], k0, k1);
                mma_f16(s[2 * ntp + 1], qa[ks], k2, k3);
            }
        }

        // causal mask (diagonal tile only)
        if (kb == qt) {
            int row0 = q0 + wq + g, row1 = row0 + 8;
            #pragma unroll
            for (int nt = 0; nt < 8; nt++) {
                int c0 = s0 + nt * 8 + 2 * tig;
                if (c0     > row0) s[nt][0] = -1e30f;
                if (c0 + 1 > row0) s[nt][1] = -1e30f;
                if (c0     > row1) s[nt][2] = -1e30f;
                if (c0 + 1 > row1) s[nt][3] = -1e30f;
            }
        }

        // online softmax
        float rm0 = -1e30f, rm1 = -1e30f;
        #pragma unroll
        for (int nt = 0; nt < 8; nt++) {
            rm0 = fmaxf(rm0, fmaxf(s[nt][0], s[nt][1]));
            rm1 = fmaxf(rm1, fmaxf(s[nt][2], s[nt][3]));
        }
        rm0 = fmaxf(rm0, __shfl_xor_sync(0xffffffffu, rm0, 1));
        rm0 = fmaxf(rm0, __shfl_xor_sync(0xffffffffu, rm0, 2));
        rm1 = fmaxf(rm1, __shfl_xor_sync(0xffffffffu, rm1, 1));
        rm1 = fmaxf(rm1, __shfl_xor_sync(0xffffffffu, rm1, 2));
        float mn0 = fmaxf(m0r, rm0), mn1 = fmaxf(m1r, rm1);
        float al0 = __expf(m0r - mn0), al1 = __expf(m1r - mn1);
        m0r = mn0; m1r = mn1;

        float rs0 = 0.f, rs1 = 0.f;
        #pragma unroll
        for (int nt = 0; nt < 8; nt++) {
            s[nt][0] = __expf(s[nt][0] - mn0); rs0 += s[nt][0];
            s[nt][1] = __expf(s[nt][1] - mn0); rs0 += s[nt][1];
            s[nt][2] = __expf(s[nt][2] - mn1); rs1 += s[nt][2];
            s[nt][3] = __expf(s[nt][3] - mn1); rs1 += s[nt][3];
        }
        rs0 += __shfl_xor_sync(0xffffffffu, rs0, 1);
        rs0 += __shfl_xor_sync(0xffffffffu, rs0, 2);
        rs1 += __shfl_xor_sync(0xffffffffu, rs1, 1);
        rs1 += __shfl_xor_sync(0xffffffffu, rs1, 2);
        l0r = l0r * al0 + rs0;
        l1r = l1r * al1 + rs1;

        // O = O*alpha + P @ V
        #pragma unroll
        for (int nt = 0; nt < 8; nt++) {
            o[nt][0] *= al0; o[nt][1] *= al0;
            o[nt][2] *= al1; o[nt][3] *= al1;
        }
        #pragma unroll
        for (int ks = 0; ks < 4; ks++) {
            uint32_t pa[4];
            pa[0] = packh(s[2 * ks][0],     s[2 * ks][1]);
            pa[1] = packh(s[2 * ks][2],     s[2 * ks][3]);
            pa[2] = packh(s[2 * ks + 1][0], s[2 * ks + 1][1]);
            pa[3] = packh(s[2 * ks + 1][2], s[2 * ks + 1][3]);
            #pragma unroll
            for (int ntp = 0; ntp < 4; ntp++) {
                uint32_t rowk = ks * 16 + vmk * 8 + vrow;
                uint32_t coln = ntp * 16 + vmn * 8;
                uint32_t va = stb + AV_B + rowk * AROW + coln * 2;
                uint32_t v0, v1, v2, v3;
                ldsm_x4_t(v0, v1, v2, v3, va);
                mma_f16(o[2 * ntp],     pa, v0, v1);
                mma_f16(o[2 * ntp + 1], pa, v2, v3);
            }
        }
    }

    // normalize + write ctx as bf16 hi/lo (feeds GEMM2 directly)
    float inv0 = 1.0f / l0r, inv1 = 1.0f / l1r;
    int row0 = q0 + wq + g;
    #pragma unroll
    for (int nt = 0; nt < 8; nt++) {
        int col = h * 64 + nt * 8 + 2 * tig;
        float v0 = o[nt][0] * inv0, v1 = o[nt][1] * inv0;
        float v2 = o[nt][2] * inv1, v3 = o[nt][3] * inv1;
        __nv_bfloat16 h0, l0, h1, l1;
        bsplit(v0, h0, l0); bsplit(v1, h1, l1);
        *(__nv_bfloat162*)&g_Ah[(size_t)row0 * E_DIM + col] = __nv_bfloat162{h0, h1};
        *(__nv_bfloat162*)&g_Al[(size_t)row0 * E_DIM + col] = __nv_bfloat162{l0, l1};
        bsplit(v2, h0, l0); bsplit(v3, h1, l1);
        *(__nv_bfloat162*)&g_Ah[(size_t)(row0 + 8) * E_DIM + col] = __nv_bfloat162{h0, h1};
        *(__nv_bfloat162*)&g_Al[(size_t)(row0 + 8) * E_DIM + col] = __nv_bfloat162{l0, l1};
    }
}

// ---------------- launch ----------------
extern "C" void kernel_launch(void* const* d_in, const int* in_sizes, int n_in,
                              void* d_out, int out_size) {
    const float* hidden = (const float*)d_in[0];
    const float* Wq     = (const float*)d_in[1];
    const float* Wk     = (const float*)d_in[2];
    const float* Wv     = (const float*)d_in[3];
    const float* q2l    = (const float*)d_in[4];
    const float* vup    = (const float*)d_in[5];
    const float* Wout   = (const float*)d_in[6];
    float* out = (float*)d_out;

    void *w1h, *w1l, *w2h, *w2l, *ah, *al;
    cudaGetSymbolAddress(&w1h, g_W1Th); cudaGetSymbolAddress(&w1l, g_W1Tl);
    cudaGetSymbolAddress(&w2h, g_W2Th); cudaGetSymbolAddress(&w2l, g_W2Tl);
    cudaGetSymbolAddress(&ah,  g_Ah);   cudaGetSymbolAddress(&al,  g_Al);

    cudaFuncSetAttribute(gemm_bf3, cudaFuncAttributeMaxDynamicSharedMemorySize, GEMM_SMEM);
    cudaFuncSetAttribute(attn_mma, cudaFuncAttributeMaxDynamicSharedMemorySize, ATTN_SMEM);

    prep_w1_kernel<<<dim3(16, 16), 256>>>(Wq, q2l);
    prep_kv_kernel<<<256, 256>>>(Wk, Wv);
    prep_w2_kernel<<<dim3(16, 16), 256>>>(vup, Wout);

    split_kernel<<<T_SEQ * E_DIM / 1024, 256>>>(hidden, (__nv_bfloat16*)ah, (__nv_bfloat16*)al);

    // GEMM1: epilogue emits fp16 Q/K/V directly (mode 1)
    gemm_bf3<<<dim3(NMID / 64, T_SEQ / 128), 256, GEMM_SMEM>>>(
        (const __nv_bfloat16*)ah, (const __nv_bfloat16*)al,
        (const __nv_bfloat16*)w1h, (const __nv_bfloat16*)w1l,
        out /*unused in mode 1*/, NMID, E_DIM, 1);

    // attention: 64-row q tiles, writes bf16 hi/lo ctx into g_Ah/g_Al
    attn_mma<<<dim3(T_SEQ / 64, H_NUM), 128, ATTN_SMEM>>>();

    // GEMM2 consumes g_Ah/g_Al directly
    gemm_bf3<<<dim3(E_DIM / 64, T_SEQ / 128), 256, GEMM_SMEM>>>(
        (const __nv_bfloat16*)ah, (const __nv_bfloat16*)al,
        (const __nv_bfloat16*)w2h, (const __nv_bfloat16*)w2l,
        out, E_DIM, E_DIM, 0);
}

// round 14
// speedup vs baseline: 1.6059x; 1.1460x over previous
#include <cuda_runtime.h>
#include <cuda_bf16.h>
#include <cuda_fp16.h>
#include <cstdint>

#define T_SEQ 2048
#define E_DIM 1024
#define H_NUM 16
#define L_DIM 64
#define NMID  1152   // 1024 q_lat cols + 64 latent_k + 64 latent_v

// ==================== helpers ====================
__device__ __forceinline__ void mma_bf16(float* c, const uint32_t* a, uint32_t b0, uint32_t b1) {
    asm volatile(
        "mma.sync.aligned.m16n8k16.row.col.f32.bf16.bf16.f32 "
        "{%0,%1,%2,%3}, {%4,%5,%6,%7}, {%8,%9}, {%0,%1,%2,%3};"
        : "+f"(c[0]), "+f"(c[1]), "+f"(c[2]), "+f"(c[3])
        : "r"(a[0]), "r"(a[1]), "r"(a[2]), "r"(a[3]), "r"(b0), "r"(b1));
}

__device__ __forceinline__ void mma_f16(float* c, const uint32_t* a, uint32_t b0, uint32_t b1) {
    asm volatile(
        "mma.sync.aligned.m16n8k16.row.col.f32.f16.f16.f32 "
        "{%0,%1,%2,%3}, {%4,%5,%6,%7}, {%8,%9}, {%0,%1,%2,%3};"
        : "+f"(c[0]), "+f"(c[1]), "+f"(c[2]), "+f"(c[3])
        : "r"(a[0]), "r"(a[1]), "r"(a[2]), "r"(a[3]), "r"(b0), "r"(b1));
}

__device__ __forceinline__ void ldsm_x4(uint32_t& r0, uint32_t& r1, uint32_t& r2, uint32_t& r3,
                                        uint32_t addr) {
    asm volatile("ldmatrix.sync.aligned.m8n8.x4.shared.b16 {%0,%1,%2,%3}, [%4];"
                 : "=r"(r0), "=r"(r1), "=r"(r2), "=r"(r3) : "r"(addr));
}

__device__ __forceinline__ void ldsm_x4_t(uint32_t& r0, uint32_t& r1, uint32_t& r2, uint32_t& r3,
                                          uint32_t addr) {
    asm volatile("ldmatrix.sync.aligned.m8n8.x4.trans.shared.b16 {%0,%1,%2,%3}, [%4];"
                 : "=r"(r0), "=r"(r1), "=r"(r2), "=r"(r3) : "r"(addr));
}

__device__ __forceinline__ uint32_t smem_u32(const void* p) {
    uint32_t a;
    asm("{ .reg .u64 t; cvta.to.shared.u64 t, %1; cvt.u32.u64 %0, t; }" : "=r"(a) : "l"(p));
    return a;
}

__device__ __forceinline__ void cp_async16(uint32_t dst, const void* src) {
    asm volatile("cp.async.cg.shared.global [%0], [%1], 16;" :: "r"(dst), "l"(src));
}
#define CP_COMMIT()  asm volatile("cp.async.commit_group;" ::: "memory")
#define CP_WAIT(N)   asm volatile("cp.async.wait_group %0;" :: "n"(N) : "memory")

__device__ __forceinline__ void bsplit(float x, __nv_bfloat16& h, __nv_bfloat16& l) {
    h = __float2bfloat16_rn(x);
    l = __float2bfloat16_rn(x - __bfloat162float(h));
}

__device__ __forceinline__ void hsplit(float x, __half& h, __half& l) {
    h = __float2half_rn(x);
    l = __float2half_rn(x - __half2float(h));
}

__device__ __forceinline__ uint32_t packh(float a, float b) {
    __half2 t = __floats2half2_rn(a, b);
    return *(uint32_t*)&t;
}

// ex2 on packed fp16 pair
__device__ __forceinline__ uint32_t ex2_h2(uint32_t x) {
    uint32_t d;
    asm("ex2.approx.f16x2 %0, %1;" : "=r"(d) : "r"(x));
    return d;
}

__device__ __forceinline__ float ex2_f32(float x) {
    float d;
    asm("ex2.approx.ftz.f32 %0, %1;" : "=f"(d) : "f"(x));
    return d;
}

#define QSCALE 0.1803368801111137f   // 0.125 * log2(e)

// ==================== device scratch ====================
__device__ __nv_bfloat16 g_W1Th[NMID * E_DIM], g_W1Tl[NMID * E_DIM];
__device__ __half g_W2h[E_DIM * E_DIM];                 // W2 single fp16
__device__ __nv_bfloat16 g_Ah[T_SEQ * E_DIM],  g_Al[T_SEQ * E_DIM];  // hidden bf16 hi/lo
__device__ __half g_Ch[T_SEQ * E_DIM], g_Cl[T_SEQ * E_DIM];          // ctx fp16 hi/lo
__device__ __half g_Q[T_SEQ * 1024];   // q_lat * 0.125*log2e, fp16
__device__ __half g_K[T_SEQ * 64];     // latent_k, fp16
__device__ __half g_V[T_SEQ * 64];     // latent_v, fp16

// ---------------- split A: bf16 hi/lo decomposition ----------------
__global__ __launch_bounds__(256) void split_kernel(const float* __restrict__ src,
                                                    __nv_bfloat16* __restrict__ hi,
                                                    __nv_bfloat16* __restrict__ lo) {
    int i = (blockIdx.x * 256 + threadIdx.x) * 4;
    float4 v = *(const float4*)&src[i];
    __nv_bfloat16 h[4], l[4];
    bsplit(v.x, h[0], l[0]); bsplit(v.y, h[1], l[1]);
    bsplit(v.z, h[2], l[2]); bsplit(v.w, h[3], l[3]);
    *(__nv_bfloat162*)&hi[i]     = __nv_bfloat162{h[0], h[1]};
    *(__nv_bfloat162*)&hi[i + 2] = __nv_bfloat162{h[2], h[3]};
    *(__nv_bfloat162*)&lo[i]     = __nv_bfloat162{l[0], l[1]};
    *(__nv_bfloat162*)&lo[i + 2] = __nv_bfloat162{l[2], l[3]};
}

// ---------------- prep 1 ----------------
__global__ __launch_bounds__(256) void prep_w1_kernel(const float* __restrict__ Wq,
                                                      const float* __restrict__ q2l) {
    __shared__ float Wqs[64][65];
    __shared__ float Qls[64][65];
    const int h  = blockIdx.y;
    const int e0 = blockIdx.x * 64;
    const int tid = threadIdx.x, tx = tid & 15, ty = tid >> 4;

    #pragma unroll
    for (int i = 0; i < 16; i++) {
        int lin = tid + i * 256;
        int c = lin & 63, r = lin >> 6;
        Wqs[r][c] = Wq[(h * 64 + r) * E_DIM + e0 + c];
        Qls[r][c] = q2l[(h * 64 + r) * 64 + c];
    }
    __syncthreads();

    float acc[4][4];
    #pragma unroll
    for (int i = 0; i < 4; i++)
        #pragma unroll
        for (int j = 0; j < 4; j++) acc[i][j] = 0.f;

    #pragma unroll 8
    for (int d = 0; d < 64; d++) {
        float a[4], b[4];
        #pragma unroll
        for (int i = 0; i < 4; i++) a[i] = Wqs[d][ty * 4 + i];
        #pragma unroll
        for (int j = 0; j < 4; j++) b[j] = Qls[d][tx * 4 + j];
        #pragma unroll
        for (int i = 0; i < 4; i++)
            #pragma unroll
            for (int j = 0; j < 4; j++) acc[i][j] += a[i] * b[j];
    }
    #pragma unroll
    for (int j = 0; j < 4; j++)
        #pragma unroll
        for (int i = 0; i < 4; i++) {
            int idx = (h * 64 + tx * 4 + j) * E_DIM + e0 + ty * 4 + i;
            __nv_bfloat16 hf, lf; bsplit(acc[i][j], hf, lf);
            g_W1Th[idx] = hf; g_W1Tl[idx] = lf;
        }
}

// ---------------- prep 2 ----------------
__global__ __launch_bounds__(256) void prep_kv_kernel(const float* __restrict__ Wk,
                                                      const float* __restrict__ Wv) {
    int idx = blockIdx.x * 256 + threadIdx.x;   // 64 * 1024
    __nv_bfloat16 hf, lf;
    bsplit(Wk[idx], hf, lf);
    g_W1Th[1024 * E_DIM + idx] = hf; g_W1Tl[1024 * E_DIM + idx] = lf;
    bsplit(Wv[idx], hf, lf);
    g_W1Th[1088 * E_DIM + idx] = hf; g_W1Tl[1088 * E_DIM + idx] = lf;
}

// ---------------- prep 3: W2 single fp16 ----------------
__global__ __launch_bounds__(256) void prep_w2_kernel(const float* __restrict__ vup,
                                                      const float* __restrict__ Wout) {
    __shared__ __align__(16) float Wos[64][68];
    __shared__ __align__(16) float Vus[64][68];
    const int h  = blockIdx.y;
    const int e0 = blockIdx.x * 64;
    const int tid = threadIdx.x, tx = tid & 15, ty = tid >> 4;

    #pragma unroll
    for (int i = 0; i < 16; i++) {
        int lin = tid + i * 256;
        int c = lin & 63, r = lin >> 6;
        Wos[r][c] = Wout[(e0 + r) * E_DIM + h * 64 + c];
        Vus[r][c] = vup[(h * 64 + r) * 64 + c];
    }
    __syncthreads();

    float acc[4][4];
    #pragma unroll
    for (int i = 0; i < 4; i++)
        #pragma unroll
        for (int j = 0; j < 4; j++) acc[i][j] = 0.f;

    #pragma unroll
    for (int d4 = 0; d4 < 16; d4++) {
        float4 a[4], b[4];
        #pragma unroll
        for (int i = 0; i < 4; i++) a[i] = *(const float4*)&Vus[ty * 4 + i][d4 * 4];
        #pragma unroll
        for (int j = 0; j < 4; j++) b[j] = *(const float4*)&Wos[tx * 4 + j][d4 * 4];
        #pragma unroll
        for (int i = 0; i < 4; i++)
            #pragma unroll
            for (int j = 0; j < 4; j++)
                acc[i][j] += a[i].x * b[j].x + a[i].y * b[j].y +
                             a[i].z * b[j].z + a[i].w * b[j].w;
    }
    #pragma unroll
    for (int j = 0; j < 4; j++)
        #pragma unroll
        for (int i = 0; i < 4; i++) {
            int idx = (e0 + tx * 4 + j) * E_DIM + h * 64 + ty * 4 + i;
            g_W2h[idx] = __float2half_rn(acc[i][j]);
        }
}

// ==================== GEMM1: bf16 3-term, 3-stage ring (validated R12) ==============
#define ROWB 80
#define SA_H 0
#define SA_L (128 * ROWB)
#define SB_H (2 * 128 * ROWB)
#define SB_L (SB_H + 64 * ROWB)
#define SSZ  (SB_L + 64 * ROWB)        // 30720 B
#define GEMM_SMEM (3 * SSZ)

__global__ __launch_bounds__(256, 2) void gemm_bf3(const __nv_bfloat16* __restrict__ Ah,
                                                   const __nv_bfloat16* __restrict__ Al,
                                                   const __nv_bfloat16* __restrict__ Bh,
                                                   const __nv_bfloat16* __restrict__ Bl,
                                                   int N, int K) {
    extern __shared__ char gsm[];
    const uint32_t sbase = smem_u32(gsm);

    const int tid = threadIdx.x;
    const int wid = tid >> 5, lane = tid & 31;
    const int g = lane >> 2, tig = lane & 3;
    const int wm = wid & 3, wn = wid >> 2;
    const int m0 = blockIdx.y * 128;
    const int n0 = blockIdx.x * 64;
    const int nst = K >> 5;

    const uint32_t aRow = lane & 15;
    const uint32_t aSel = ((lane >> 4) & 1) * 16;
    const uint32_t bRow = (lane & 7) + ((lane & 16) ? 8 : 0);
    const uint32_t bSel = (lane & 8) ? 16 : 0;

    float c[2][4][4];
    #pragma unroll
    for (int mt = 0; mt < 2; mt++)
        #pragma unroll
        for (int nt = 0; nt < 4; nt++)
            #pragma unroll
            for (int j = 0; j < 4; j++) c[mt][nt][j] = 0.f;

    auto fetch = [&](int k0, int b) {
        const uint32_t s0 = sbase + (uint32_t)(b * SSZ);
        #pragma unroll
        for (int i = 0; i < 6; i++) {
            int idx = tid + i * 256;
            if (idx < 1024) {
                int t = idx >> 9;
                int r = (idx & 511) >> 2, cc = idx & 3;
                const __nv_bfloat16* src = (t ? Al : Ah) + (size_t)(m0 + r) * K + k0 + cc * 8;
                cp_async16(s0 + (t ? SA_L : SA_H) + r * ROWB + cc * 16, src);
            } else {
                int t = (idx - 1024) >> 8;
                int r = ((idx - 1024) & 255) >> 2, cc = idx & 3;
                const __nv_bfloat16* src = (t ? Bl : Bh) + (size_t)(n0 + r) * K + k0 + cc * 8;
                cp_async16(s0 + (t ? SB_L : SB_H) + r * ROWB + cc * 16, src);
            }
        }
        CP_COMMIT();
    };

    fetch(0, 0);
    fetch(32, 1);

    for (int s = 0; s < nst; s++) {
        const int buf = s - (s / 3) * 3;
        if (s + 1 < nst) CP_WAIT(1);
        else             CP_WAIT(0);
        __syncthreads();
        if (s + 2 < nst) {
            int nb = (s + 2) - ((s + 2) / 3) * 3;
            fetch((s + 2) << 5, nb);
        }

        const uint32_t sb = sbase + (uint32_t)(buf * SSZ);
        #pragma unroll
        for (int ks = 0; ks < 2; ks++) {
            uint32_t ah[2][4], al[2][4];
            #pragma unroll
            for (int mt = 0; mt < 2; mt++) {
                uint32_t ra = (wm * 32 + mt * 16 + aRow) * ROWB + ks * 32 + aSel;
                ldsm_x4(ah[mt][0], ah[mt][1], ah[mt][2], ah[mt][3], sb + SA_H + ra);
                ldsm_x4(al[mt][0], al[mt][1], al[mt][2], al[mt][3], sb + SA_L + ra);
            }
            #pragma unroll
            for (int ntp = 0; ntp < 2; ntp++) {
                uint32_t rb = (wn * 32 + ntp * 16 + bRow) * ROWB + ks * 32 + bSel;
                uint32_t h0, h1, h2, h3, l0, l1, l2, l3;
                ldsm_x4(h0, h1, h2, h3, sb + SB_H + rb);
                ldsm_x4(l0, l1, l2, l3, sb + SB_L + rb);
                #pragma unroll
                for (int mt = 0; mt < 2; mt++) {
                    float* c0 = c[mt][2 * ntp];
                    float* c1 = c[mt][2 * ntp + 1];
                    mma_bf16(c0, ah[mt], h0, h1);
                    mma_bf16(c0, ah[mt], l0, l1);
                    mma_bf16(c0, al[mt], h0, h1);
                    mma_bf16(c1, ah[mt], h2, h3);
                    mma_bf16(c1, ah[mt], l2, l3);
                    mma_bf16(c1, al[mt], h2, h3);
                }
            }
        }
    }

    // epilogue: q_lat -> g_Q fp16 (x 0.125*log2e), K -> g_K, V -> g_V
    #pragma unroll
    for (int mt = 0; mt < 2; mt++) {
        int row0 = m0 + wm * 32 + mt * 16 + g;
        #pragma unroll
        for (int nt = 0; nt < 4; nt++) {
            int col = n0 + wn * 32 + nt * 8 + 2 * tig;
            float v0 = c[mt][nt][0], v1 = c[mt][nt][1];
            float v2 = c[mt][nt][2], v3 = c[mt][nt][3];
            if (col < 1024) {
                *(uint32_t*)&g_Q[(size_t)row0 * 1024 + col] =
                    packh(v0 * QSCALE, v1 * QSCALE);
                *(uint32_t*)&g_Q[(size_t)(row0 + 8) * 1024 + col] =
                    packh(v2 * QSCALE, v3 * QSCALE);
            } else if (col < 1088) {
                int kc = col - 1024;
                *(uint32_t*)&g_K[(size_t)row0 * 64 + kc]       = packh(v0, v1);
                *(uint32_t*)&g_K[(size_t)(row0 + 8) * 64 + kc] = packh(v2, v3);
            } else {
                int vc = col - 1088;
                *(uint32_t*)&g_V[(size_t)row0 * 64 + vc]       = packh(v0, v1);
                *(uint32_t*)&g_V[(size_t)(row0 + 8) * 64 + vc] = packh(v2, v3);
            }
        }
    }
}

// ==================== GEMM2: fp16 2-term (Ch+Cl) x W2h, 3-stage ring ================
#define SSZ2   ((2 * 128 + 64) * ROWB)   // 25600 B
#define S2A_H  0
#define S2A_L  (128 * ROWB)
#define S2B    (2 * 128 * ROWB)
#define GEMM2_SMEM (3 * SSZ2)

__global__ __launch_bounds__(256, 2) void gemm_2t(const __half* __restrict__ Ah,
                                                  const __half* __restrict__ Al,
                                                  const __half* __restrict__ Bh,
                                                  float* __restrict__ C,
                                                  int N, int K) {
    extern __shared__ char gsm[];
    const uint32_t sbase = smem_u32(gsm);

    const int tid = threadIdx.x;
    const int wid = tid >> 5, lane = tid & 31;
    const int g = lane >> 2, tig = lane & 3;
    const int wm = wid & 3, wn = wid >> 2;
    const int m0 = blockIdx.y * 128;
    const int n0 = blockIdx.x * 64;
    const int nst = K >> 5;

    const uint32_t aRow = lane & 15;
    const uint32_t aSel = ((lane >> 4) & 1) * 16;
    const uint32_t bRow = (lane & 7) + ((lane & 16) ? 8 : 0);
    const uint32_t bSel = (lane & 8) ? 16 : 0;

    float c[2][4][4];
    #pragma unroll
    for (int mt = 0; mt < 2; mt++)
        #pragma unroll
        for (int nt = 0; nt < 4; nt++)
            #pragma unroll
            for (int j = 0; j < 4; j++) c[mt][nt][j] = 0.f;

    auto fetch = [&](int k0, int b) {
        const uint32_t s0 = sbase + (uint32_t)(b * SSZ2);
        #pragma unroll
        for (int i = 0; i < 5; i++) {
            int idx = tid + i * 256;
            if (idx < 1024) {
                int t = idx >> 9;
                int r = (idx & 511) >> 2, cc = idx & 3;
                const __half* src = (t ? Al : Ah) + (size_t)(m0 + r) * K + k0 + cc * 8;
                cp_async16(s0 + (t ? S2A_L : S2A_H) + r * ROWB + cc * 16, src);
            } else {
                int r = ((idx - 1024) & 255) >> 2, cc = idx & 3;
                const __half* src = Bh + (size_t)(n0 + r) * K + k0 + cc * 8;
                cp_async16(s0 + S2B + r * ROWB + cc * 16, src);
            }
        }
        CP_COMMIT();
    };

    fetch(0, 0);
    fetch(32, 1);

    for (int s = 0; s < nst; s++) {
        const int buf = s - (s / 3) * 3;
        if (s + 1 < nst) CP_WAIT(1);
        else             CP_WAIT(0);
        __syncthreads();
        if (s + 2 < nst) {
            int nb = (s + 2) - ((s + 2) / 3) * 3;
            fetch((s + 2) << 5, nb);
        }

        const uint32_t sb = sbase + (uint32_t)(buf * SSZ2);
        #pragma unroll
        for (int ks = 0; ks < 2; ks++) {
            uint32_t ah[2][4], al[2][4];
            #pragma unroll
            for (int mt = 0; mt < 2; mt++) {
                uint32_t ra = (wm * 32 + mt * 16 + aRow) * ROWB + ks * 32 + aSel;
                ldsm_x4(ah[mt][0], ah[mt][1], ah[mt][2], ah[mt][3], sb + S2A_H + ra);
                ldsm_x4(al[mt][0], al[mt][1], al[mt][2], al[mt][3], sb + S2A_L + ra);
            }
            #pragma unroll
            for (int ntp = 0; ntp < 2; ntp++) {
                uint32_t rb = (wn * 32 + ntp * 16 + bRow) * ROWB + ks * 32 + bSel;
                uint32_t h0, h1, h2, h3;
                ldsm_x4(h0, h1, h2, h3, sb + S2B + rb);
                #pragma unroll
                for (int mt = 0; mt < 2; mt++) {
                    float* c0 = c[mt][2 * ntp];
                    float* c1 = c[mt][2 * ntp + 1];
                    mma_f16(c0, ah[mt], h0, h1);
                    mma_f16(c0, al[mt], h0, h1);
                    mma_f16(c1, ah[mt], h2, h3);
                    mma_f16(c1, al[mt], h2, h3);
                }
            }
        }
    }

    #pragma unroll
    for (int mt = 0; mt < 2; mt++) {
        int row0 = m0 + wm * 32 + mt * 16 + g;
        #pragma unroll
        for (int nt = 0; nt < 4; nt++) {
            int col = n0 + wn * 32 + nt * 8 + 2 * tig;
            *(float2*)&C[(size_t)row0 * N + col] =
                make_float2(c[mt][nt][0], c[mt][nt][1]);
            *(float2*)&C[(size_t)(row0 + 8) * N + col] =
                make_float2(c[mt][nt][2], c[mt][nt][3]);
        }
    }
}

// ==================== fp16 flash attention, log2 softmax + ones-column l ============
#define AROW 144
#define AQ_B 0
#define AKV_B (64 * AROW)
#define AST_B (2 * 64 * AROW)
#define AV_B  (64 * AROW)
#define ATTN_SMEM (AKV_B + 2 * AST_B)  // 46080

__global__ __launch_bounds__(128, 4) void attn_mma() {
    extern __shared__ char asm_[];
    const uint32_t sbase = smem_u32(asm_);
    const int tid = threadIdx.x;
    const int wid = tid >> 5, lane = tid & 31;
    const int g = lane >> 2, tig = lane & 3;
    const int wq = wid * 16;
    const int qt = (int)gridDim.x - 1 - (int)blockIdx.x;  // heavy first
    const int h  = blockIdx.y;
    const int q0 = qt * 64;
    const int nkv = qt + 1;

    const uint32_t aRow = lane & 15;
    const uint32_t aSel = ((lane >> 4) & 1) * 16;
    const uint32_t bRow = (lane & 7) + ((lane & 16) ? 8 : 0);
    const uint32_t bSel = (lane & 8) ? 16 : 0;
    const int vrow = lane & 7;
    const int vmk  = (lane >> 3) & 1;
    const int vmn  = (lane >> 4) & 1;

    // ones B-fragment for the l column: n-group lane g==0 holds B[k][0]=1
    const uint32_t ones = (g == 0) ? 0x3C003C00u : 0u;

    auto fetch_kv = [&](int blk, int b) {
        const uint32_t st = sbase + (uint32_t)(AKV_B + b * AST_B);
        #pragma unroll
        for (int i = 0; i < 8; i++) {
            int idx = tid + i * 128;
            int isV = idx >> 9;
            int r = (idx & 511) >> 3, cc = idx & 7;
            const __half* src = (isV ? g_V : g_K) + (size_t)(blk * 64 + r) * 64 + cc * 8;
            cp_async16(st + (isV ? AV_B : 0) + r * AROW + cc * 16, src);
        }
        CP_COMMIT();
    };

    fetch_kv(0, 0);
    {
        #pragma unroll
        for (int i = 0; i < 4; i++) {
            int idx = tid + i * 128;
            int r = idx >> 3, cc = idx & 7;
            cp_async16(sbase + (uint32_t)(AQ_B + r * AROW + cc * 16),
                       &g_Q[(size_t)(q0 + r) * 1024 + h * 64 + cc * 8]);
        }
        CP_COMMIT();
    }
    CP_WAIT(0);
    __syncthreads();

    uint32_t qa[4][4];
    #pragma unroll
    for (int ks = 0; ks < 4; ks++) {
        uint32_t ra = sbase + (uint32_t)(AQ_B + (wq + aRow) * AROW + ks * 32) + aSel;
        ldsm_x4(qa[ks][0], qa[ks][1], qa[ks][2], qa[ks][3], ra);
    }

    float o[8][4], ol[4];
    #pragma unroll
    for (int nt = 0; nt < 8; nt++)
        #pragma unroll
        for (int j = 0; j < 4; j++) o[nt][j] = 0.f;
    ol[0] = ol[1] = ol[2] = ol[3] = 0.f;
    float m0r = -1e30f, m1r = -1e30f;

    for (int kb = 0; kb < nkv; kb++) {
        const int buf = kb & 1;
        if (kb > 0) {
            CP_WAIT(0);
            __syncthreads();
        }
        if (kb + 1 < nkv) fetch_kv(kb + 1, buf ^ 1);

        const uint32_t stb = sbase + (uint32_t)(AKV_B + buf * AST_B);
        const int s0 = kb * 64;

        // S = Q @ K^T  (logits in log2 domain; Q pre-scaled by 0.125*log2e)
        float s[8][4];
        #pragma unroll
        for (int nt = 0; nt < 8; nt++)
            s[nt][0] = s[nt][1] = s[nt][2] = s[nt][3] = 0.f;
        #pragma unroll
        for (int ntp = 0; ntp < 4; ntp++) {
            #pragma unroll
            for (int ks = 0; ks < 4; ks++) {
                uint32_t addr = stb + (uint32_t)((ntp * 16 + bRow) * AROW + ks * 32) + bSel;
                uint32_t k0, k1, k2, k3;
                ldsm_x4(k0, k1, k2, k3, addr);
                mma_f16(s[2 * ntp],     qa[ks], k0, k1);
                mma_f16(s[2 * ntp + 1], qa[ks], k2, k3);
            }
        }

        if (kb == qt) {
            int row0 = q0 + wq + g, row1 = row0 + 8;
            #pragma unroll
            for (int nt = 0; nt < 8; nt++) {
                int c0 = s0 + nt * 8 + 2 * tig;
                if (c0     > row0) s[nt][0] = -1e30f;
                if (c0 + 1 > row0) s[nt][1] = -1e30f;
                if (c0     > row1) s[nt][2] = -1e30f;
                if (c0 + 1 > row1) s[nt][3] = -1e30f;
            }
        }

        // max reduce (log2 domain)
        float rm0 = -1e30f, rm1 = -1e30f;
        #pragma unroll
        for (int nt = 0; nt < 8; nt++) {
            rm0 = fmaxf(rm0, fmaxf(s[nt][0], s[nt][1]));
            rm1 = fmaxf(rm1, fmaxf(s[nt][2], s[nt][3]));
        }
        rm0 = fmaxf(rm0, __shfl_xor_sync(0xffffffffu, rm0, 1));
        rm0 = fmaxf(rm0, __shfl_xor_sync(0xffffffffu, rm0, 2));
        rm1 = fmaxf(rm1, __shfl_xor_sync(0xffffffffu, rm1, 1));
        rm1 = fmaxf(rm1, __shfl_xor_sync(0xffffffffu, rm1, 2));
        float mn0 = fmaxf(m0r, rm0), mn1 = fmaxf(m1r, rm1);
        float al0 = ex2_f32(m0r - mn0), al1 = ex2_f32(m1r - mn1);
        m0r = mn0; m1r = mn1;

        // O *= alpha (including l accumulators)
        #pragma unroll
        for (int nt = 0; nt < 8; nt++) {
            o[nt][0] *= al0; o[nt][1] *= al0;
            o[nt][2] *= al1; o[nt][3] *= al1;
        }
        ol[0] *= al0; ol[1] *= al0; ol[2] *= al1; ol[3] *= al1;

        // P fragments: ex2 on packed fp16 pairs; PV (+ ones column accumulates l)
        #pragma unroll
        for (int ks = 0; ks < 4; ks++) {
            uint32_t pa[4];
            pa[0] = ex2_h2(packh(s[2 * ks][0]     - mn0, s[2 * ks][1]     - mn0));
            pa[1] = ex2_h2(packh(s[2 * ks][2]     - mn1, s[2 * ks][3]     - mn1));
            pa[2] = ex2_h2(packh(s[2 * ks + 1][0] - mn0, s[2 * ks + 1][1] - mn0));
            pa[3] = ex2_h2(packh(s[2 * ks + 1][2] - mn1, s[2 * ks + 1][3] - mn1));
            #pragma unroll
            for (int ntp = 0; ntp < 4; ntp++) {
                uint32_t rowk = ks * 16 + vmk * 8 + vrow;
                uint32_t coln = ntp * 16 + vmn * 8;
                uint32_t va = stb + AV_B + rowk * AROW + coln * 2;
                uint32_t v0, v1, v2, v3;
                ldsm_x4_t(v0, v1, v2, v3, va);
                mma_f16(o[2 * ntp],     pa, v0, v1);
                mma_f16(o[2 * ntp + 1], pa, v2, v3);
            }
            mma_f16(ol, pa, ones, ones);   // l += P @ 1
        }
    }

    // l lives in lanes tig==0 (column 0 of the ones block); broadcast within quad
    float l0r = __shfl_sync(0xffffffffu, ol[0], lane & 28);
    float l1r = __shfl_sync(0xffffffffu, ol[2], lane & 28);

    // normalize + write ctx as fp16 hi/lo (feeds GEMM2 2-term)
    float inv0 = 1.0f / l0r, inv1 = 1.0f / l1r;
    int row0 = q0 + wq + g;
    #pragma unroll
    for (int nt = 0; nt < 8; nt++) {
        int col = h * 64 + nt * 8 + 2 * tig;
        float v0 = o[nt][0] * inv0, v1 = o[nt][1] * inv0;
        float v2 = o[nt][2] * inv1, v3 = o[nt][3] * inv1;
        __half h0, l0, h1, l1;
        hsplit(v0, h0, l0); hsplit(v1, h1, l1);
        *(__half2*)&g_Ch[(size_t)row0 * E_DIM + col] = __half2{h0, h1};
        *(__half2*)&g_Cl[(size_t)row0 * E_DIM + col] = __half2{l0, l1};
        hsplit(v2, h0, l0); hsplit(v3, h1, l1);
        *(__half2*)&g_Ch[(size_t)(row0 + 8) * E_DIM + col] = __half2{h0, h1};
        *(__half2*)&g_Cl[(size_t)(row0 + 8) * E_DIM + col] = __half2{l0, l1};
    }
}

// ---------------- launch ----------------
extern "C" void kernel_launch(void* const* d_in, const int* in_sizes, int n_in,
                              void* d_out, int out_size) {
    const float* hidden = (const float*)d_in[0];
    const float* Wq     = (const float*)d_in[1];
    const float* Wk     = (const float*)d_in[2];
    const float* Wv     = (const float*)d_in[3];
    const float* q2l    = (const float*)d_in[4];
    const float* vup    = (const float*)d_in[5];
    const float* Wout   = (const float*)d_in[6];
    float* out = (float*)d_out;

    void *w1h, *w1l, *w2h, *ah, *al, *ch, *cl;
    cudaGetSymbolAddress(&w1h, g_W1Th); cudaGetSymbolAddress(&w1l, g_W1Tl);
    cudaGetSymbolAddress(&w2h, g_W2h);
    cudaGetSymbolAddress(&ah,  g_Ah);   cudaGetSymbolAddress(&al,  g_Al);
    cudaGetSymbolAddress(&ch,  g_Ch);   cudaGetSymbolAddress(&cl,  g_Cl);

    cudaFuncSetAttribute(gemm_bf3, cudaFuncAttributeMaxDynamicSharedMemorySize, GEMM_SMEM);
    cudaFuncSetAttribute(gemm_2t,  cudaFuncAttributeMaxDynamicSharedMemorySize, GEMM2_SMEM);
    cudaFuncSetAttribute(attn_mma, cudaFuncAttributeMaxDynamicSharedMemorySize, ATTN_SMEM);

    prep_w1_kernel<<<dim3(16, 16), 256>>>(Wq, q2l);
    prep_kv_kernel<<<256, 256>>>(Wk, Wv);
    prep_w2_kernel<<<dim3(16, 16), 256>>>(vup, Wout);

    split_kernel<<<T_SEQ * E_DIM / 1024, 256>>>(hidden, (__nv_bfloat16*)ah, (__nv_bfloat16*)al);

    // GEMM1 (bf16 3-term): emits fp16 Q (log2-scaled) / K / V
    gemm_bf3<<<dim3(NMID / 64, T_SEQ / 128), 256, GEMM_SMEM>>>(
        (const __nv_bfloat16*)ah, (const __nv_bfloat16*)al,
        (const __nv_bfloat16*)w1h, (const __nv_bfloat16*)w1l,
        NMID, E_DIM);

    // attention: 64-row q tiles, log2 softmax, l via ones-column
    attn_mma<<<dim3(T_SEQ / 64, H_NUM), 128, ATTN_SMEM>>>();

    // GEMM2 (fp16 2-term): out = (Ch + Cl) @ W2h^T
    gemm_2t<<<dim3(E_DIM / 64, T_SEQ / 128), 256, GEMM2_SMEM>>>(
        (const __half*)ch, (const __half*)cl, (const __half*)w2h,
        out, E_DIM, E_DIM);
}

// round 15
// speedup vs baseline: 1.8081x; 1.1259x over previous
#include <cuda_runtime.h>
#include <cuda_bf16.h>
#include <cuda_fp16.h>
#include <cstdint>

#define T_SEQ 2048
#define E_DIM 1024
#define H_NUM 16
#define L_DIM 64
#define NMID  1152   // 1024 q_lat cols + 64 latent_k + 64 latent_v

// ==================== helpers ====================
__device__ __forceinline__ void mma_f16(float* c, const uint32_t* a, uint32_t b0, uint32_t b1) {
    asm volatile(
        "mma.sync.aligned.m16n8k16.row.col.f32.f16.f16.f32 "
        "{%0,%1,%2,%3}, {%4,%5,%6,%7}, {%8,%9}, {%0,%1,%2,%3};"
        : "+f"(c[0]), "+f"(c[1]), "+f"(c[2]), "+f"(c[3])
        : "r"(a[0]), "r"(a[1]), "r"(a[2]), "r"(a[3]), "r"(b0), "r"(b1));
}

__device__ __forceinline__ void ldsm_x4(uint32_t& r0, uint32_t& r1, uint32_t& r2, uint32_t& r3,
                                        uint32_t addr) {
    asm volatile("ldmatrix.sync.aligned.m8n8.x4.shared.b16 {%0,%1,%2,%3}, [%4];"
                 : "=r"(r0), "=r"(r1), "=r"(r2), "=r"(r3) : "r"(addr));
}

__device__ __forceinline__ void ldsm_x4_t(uint32_t& r0, uint32_t& r1, uint32_t& r2, uint32_t& r3,
                                          uint32_t addr) {
    asm volatile("ldmatrix.sync.aligned.m8n8.x4.trans.shared.b16 {%0,%1,%2,%3}, [%4];"
                 : "=r"(r0), "=r"(r1), "=r"(r2), "=r"(r3) : "r"(addr));
}

__device__ __forceinline__ uint32_t smem_u32(const void* p) {
    uint32_t a;
    asm("{ .reg .u64 t; cvta.to.shared.u64 t, %1; cvt.u32.u64 %0, t; }" : "=r"(a) : "l"(p));
    return a;
}

__device__ __forceinline__ void cp_async16(uint32_t dst, const void* src) {
    asm volatile("cp.async.cg.shared.global [%0], [%1], 16;" :: "r"(dst), "l"(src));
}
#define CP_COMMIT()  asm volatile("cp.async.commit_group;" ::: "memory")
#define CP_WAIT(N)   asm volatile("cp.async.wait_group %0;" :: "n"(N) : "memory")

__device__ __forceinline__ void hsplit(float x, __half& h, __half& l) {
    h = __float2half_rn(x);
    l = __float2half_rn(x - __half2float(h));
}

__device__ __forceinline__ uint32_t packh(float a, float b) {
    __half2 t = __floats2half2_rn(a, b);
    return *(uint32_t*)&t;
}

__device__ __forceinline__ uint32_t ex2_h2(uint32_t x) {
    uint32_t d;
    asm("ex2.approx.f16x2 %0, %1;" : "=r"(d) : "r"(x));
    return d;
}

__device__ __forceinline__ float ex2_f32(float x) {
    float d;
    asm("ex2.approx.ftz.f32 %0, %1;" : "=f"(d) : "f"(x));
    return d;
}

#define QSCALE 0.1803368801111137f   // 0.125 * log2(e)

// ==================== device scratch ====================
__device__ __half g_W1h[NMID * E_DIM];                   // fused W1, fp16
__device__ __half g_W2h[E_DIM * E_DIM];                  // fused W2, fp16
__device__ __half g_Xh[T_SEQ * E_DIM], g_Xl[T_SEQ * E_DIM];  // hidden fp16 hi/lo
__device__ __half g_Ch[T_SEQ * E_DIM], g_Cl[T_SEQ * E_DIM];  // ctx fp16 hi/lo
__device__ __half g_Q[T_SEQ * 1024];   // q_lat * 0.125*log2e, fp16
__device__ __half g_K[T_SEQ * 64];     // latent_k, fp16
__device__ __half g_V[T_SEQ * 64];     // latent_v, fp16

// ---------------- split: fp16 hi/lo decomposition of fp32 tensor ----------------
__global__ __launch_bounds__(256) void split_kernel(const float* __restrict__ src,
                                                    __half* __restrict__ hi,
                                                    __half* __restrict__ lo) {
    int i = (blockIdx.x * 256 + threadIdx.x) * 4;
    float4 v = *(const float4*)&src[i];
    __half h[4], l[4];
    hsplit(v.x, h[0], l[0]); hsplit(v.y, h[1], l[1]);
    hsplit(v.z, h[2], l[2]); hsplit(v.w, h[3], l[3]);
    *(__half2*)&hi[i]     = __half2{h[0], h[1]};
    *(__half2*)&hi[i + 2] = __half2{h[2], h[3]};
    *(__half2*)&lo[i]     = __half2{l[0], l[1]};
    *(__half2*)&lo[i + 2] = __half2{l[2], l[3]};
}

// ---------------- prep 1: W1h[h*64+l][e] = sum_d Wq[h*64+d, e] * q2l[h,d,l] ----
__global__ __launch_bounds__(256) void prep_w1_kernel(const float* __restrict__ Wq,
                                                      const float* __restrict__ q2l) {
    __shared__ float Wqs[64][65];
    __shared__ float Qls[64][65];
    const int h  = blockIdx.y;
    const int e0 = blockIdx.x * 64;
    const int tid = threadIdx.x, tx = tid & 15, ty = tid >> 4;

    #pragma unroll
    for (int i = 0; i < 16; i++) {
        int lin = tid + i * 256;
        int c = lin & 63, r = lin >> 6;
        Wqs[r][c] = Wq[(h * 64 + r) * E_DIM + e0 + c];
        Qls[r][c] = q2l[(h * 64 + r) * 64 + c];
    }
    __syncthreads();

    float acc[4][4];
    #pragma unroll
    for (int i = 0; i < 4; i++)
        #pragma unroll
        for (int j = 0; j < 4; j++) acc[i][j] = 0.f;

    #pragma unroll 8
    for (int d = 0; d < 64; d++) {
        float a[4], b[4];
        #pragma unroll
        for (int i = 0; i < 4; i++) a[i] = Wqs[d][ty * 4 + i];
        #pragma unroll
        for (int j = 0; j < 4; j++) b[j] = Qls[d][tx * 4 + j];
        #pragma unroll
        for (int i = 0; i < 4; i++)
            #pragma unroll
            for (int j = 0; j < 4; j++) acc[i][j] += a[i] * b[j];
    }
    #pragma unroll
    for (int j = 0; j < 4; j++)
        #pragma unroll
        for (int i = 0; i < 4; i++)
            g_W1h[(h * 64 + tx * 4 + j) * E_DIM + e0 + ty * 4 + i] = __float2half_rn(acc[i][j]);
}

// ---------------- prep 2: W1h rows 1024+l / 1088+l = Wk_down / Wv_down ----
__global__ __launch_bounds__(256) void prep_kv_kernel(const float* __restrict__ Wk,
                                                      const float* __restrict__ Wv) {
    int idx = blockIdx.x * 256 + threadIdx.x;   // 64 * 1024
    g_W1h[1024 * E_DIM + idx] = __float2half_rn(Wk[idx]);
    g_W1h[1088 * E_DIM + idx] = __float2half_rn(Wv[idx]);
}

// ---------------- prep 3: W2 single fp16 ----------------
__global__ __launch_bounds__(256) void prep_w2_kernel(const float* __restrict__ vup,
                                                      const float* __restrict__ Wout) {
    __shared__ __align__(16) float Wos[64][68];
    __shared__ __align__(16) float Vus[64][68];
    const int h  = blockIdx.y;
    const int e0 = blockIdx.x * 64;
    const int tid = threadIdx.x, tx = tid & 15, ty = tid >> 4;

    #pragma unroll
    for (int i = 0; i < 16; i++) {
        int lin = tid + i * 256;
        int c = lin & 63, r = lin >> 6;
        Wos[r][c] = Wout[(e0 + r) * E_DIM + h * 64 + c];
        Vus[r][c] = vup[(h * 64 + r) * 64 + c];
    }
    __syncthreads();

    float acc[4][4];
    #pragma unroll
    for (int i = 0; i < 4; i++)
        #pragma unroll
        for (int j = 0; j < 4; j++) acc[i][j] = 0.f;

    #pragma unroll
    for (int d4 = 0; d4 < 16; d4++) {
        float4 a[4], b[4];
        #pragma unroll
        for (int i = 0; i < 4; i++) a[i] = *(const float4*)&Vus[ty * 4 + i][d4 * 4];
        #pragma unroll
        for (int j = 0; j < 4; j++) b[j] = *(const float4*)&Wos[tx * 4 + j][d4 * 4];
        #pragma unroll
        for (int i = 0; i < 4; i++)
            #pragma unroll
            for (int j = 0; j < 4; j++)
                acc[i][j] += a[i].x * b[j].x + a[i].y * b[j].y +
                             a[i].z * b[j].z + a[i].w * b[j].w;
    }
    #pragma unroll
    for (int j = 0; j < 4; j++)
        #pragma unroll
        for (int i = 0; i < 4; i++) {
            int idx = (e0 + tx * 4 + j) * E_DIM + h * 64 + ty * 4 + i;
            g_W2h[idx] = __float2half_rn(acc[i][j]);
        }
}

// ==================== unified fp16 2-term GEMM: (Ah+Al) x Bh, 3-stage ring ==========
// mode 1: GEMM1 epilogue -> g_Q (x QSCALE) / g_K / g_V.   mode 0: fp32 C store.
#define ROWB 80
#define S2A_H  0
#define S2A_L  (128 * ROWB)
#define S2B    (2 * 128 * ROWB)
#define SSZ2   ((2 * 128 + 64) * ROWB)   // 25600 B per stage
#define GEMM_SMEM (3 * SSZ2)             // 76800 B

__global__ __launch_bounds__(256, 2) void gemm_2t(const __half* __restrict__ Ah,
                                                  const __half* __restrict__ Al,
                                                  const __half* __restrict__ Bh,
                                                  float* __restrict__ C,
                                                  int N, int K, int mode) {
    extern __shared__ char gsm[];
    const uint32_t sbase = smem_u32(gsm);

    const int tid = threadIdx.x;
    const int wid = tid >> 5, lane = tid & 31;
    const int g = lane >> 2, tig = lane & 3;
    const int wm = wid & 3, wn = wid >> 2;
    const int m0 = blockIdx.y * 128;
    const int n0 = blockIdx.x * 64;
    const int nst = K >> 5;

    const uint32_t aRow = lane & 15;
    const uint32_t aSel = ((lane >> 4) & 1) * 16;
    const uint32_t bRow = (lane & 7) + ((lane & 16) ? 8 : 0);
    const uint32_t bSel = (lane & 8) ? 16 : 0;

    float c[2][4][4];
    #pragma unroll
    for (int mt = 0; mt < 2; mt++)
        #pragma unroll
        for (int nt = 0; nt < 4; nt++)
            #pragma unroll
            for (int j = 0; j < 4; j++) c[mt][nt][j] = 0.f;

    auto fetch = [&](int k0, int b) {
        const uint32_t s0 = sbase + (uint32_t)(b * SSZ2);
        #pragma unroll
        for (int i = 0; i < 5; i++) {
            int idx = tid + i * 256;
            if (idx < 1024) {
                int t = idx >> 9;
                int r = (idx & 511) >> 2, cc = idx & 3;
                const __half* src = (t ? Al : Ah) + (size_t)(m0 + r) * K + k0 + cc * 8;
                cp_async16(s0 + (t ? S2A_L : S2A_H) + r * ROWB + cc * 16, src);
            } else {
                int r = ((idx - 1024) & 255) >> 2, cc = idx & 3;
                const __half* src = Bh + (size_t)(n0 + r) * K + k0 + cc * 8;
                cp_async16(s0 + S2B + r * ROWB + cc * 16, src);
            }
        }
        CP_COMMIT();
    };

    fetch(0, 0);
    fetch(32, 1);

    for (int s = 0; s < nst; s++) {
        const int buf = s - (s / 3) * 3;
        if (s + 1 < nst) CP_WAIT(1);
        else             CP_WAIT(0);
        __syncthreads();
        if (s + 2 < nst) {
            int nb = (s + 2) - ((s + 2) / 3) * 3;
            fetch((s + 2) << 5, nb);
        }

        const uint32_t sb = sbase + (uint32_t)(buf * SSZ2);
        #pragma unroll
        for (int ks = 0; ks < 2; ks++) {
            uint32_t ah[2][4], al[2][4];
            #pragma unroll
            for (int mt = 0; mt < 2; mt++) {
                uint32_t ra = (wm * 32 + mt * 16 + aRow) * ROWB + ks * 32 + aSel;
                ldsm_x4(ah[mt][0], ah[mt][1], ah[mt][2], ah[mt][3], sb + S2A_H + ra);
                ldsm_x4(al[mt][0], al[mt][1], al[mt][2], al[mt][3], sb + S2A_L + ra);
            }
            #pragma unroll
            for (int ntp = 0; ntp < 2; ntp++) {
                uint32_t rb = (wn * 32 + ntp * 16 + bRow) * ROWB + ks * 32 + bSel;
                uint32_t h0, h1, h2, h3;
                ldsm_x4(h0, h1, h2, h3, sb + S2B + rb);
                #pragma unroll
                for (int mt = 0; mt < 2; mt++) {
                    float* c0 = c[mt][2 * ntp];
                    float* c1 = c[mt][2 * ntp + 1];
                    mma_f16(c0, ah[mt], h0, h1);
                    mma_f16(c0, al[mt], h0, h1);
                    mma_f16(c1, ah[mt], h2, h3);
                    mma_f16(c1, al[mt], h2, h3);
                }
            }
        }
    }

    #pragma unroll
    for (int mt = 0; mt < 2; mt++) {
        int row0 = m0 + wm * 32 + mt * 16 + g;
        #pragma unroll
        for (int nt = 0; nt < 4; nt++) {
            int col = n0 + wn * 32 + nt * 8 + 2 * tig;
            float v0 = c[mt][nt][0], v1 = c[mt][nt][1];
            float v2 = c[mt][nt][2], v3 = c[mt][nt][3];
            if (mode == 1) {
                if (col < 1024) {
                    *(uint32_t*)&g_Q[(size_t)row0 * 1024 + col] =
                        packh(v0 * QSCALE, v1 * QSCALE);
                    *(uint32_t*)&g_Q[(size_t)(row0 + 8) * 1024 + col] =
                        packh(v2 * QSCALE, v3 * QSCALE);
                } else if (col < 1088) {
                    int kc = col - 1024;
                    *(uint32_t*)&g_K[(size_t)row0 * 64 + kc]       = packh(v0, v1);
                    *(uint32_t*)&g_K[(size_t)(row0 + 8) * 64 + kc] = packh(v2, v3);
                } else {
                    int vc = col - 1088;
                    *(uint32_t*)&g_V[(size_t)row0 * 64 + vc]       = packh(v0, v1);
                    *(uint32_t*)&g_V[(size_t)(row0 + 8) * 64 + vc] = packh(v2, v3);
                }
            } else {
                *(float2*)&C[(size_t)row0 * N + col]       = make_float2(v0, v1);
                *(float2*)&C[(size_t)(row0 + 8) * N + col] = make_float2(v2, v3);
            }
        }
    }
}

// ==================== fp16 flash attention, log2 softmax + ones-column l ============
#define AROW 144
#define AQ_B 0
#define AKV_B (64 * AROW)
#define AST_B (2 * 64 * AROW)
#define AV_B  (64 * AROW)
#define ATTN_SMEM (AKV_B + 2 * AST_B)  // 46080

__global__ __launch_bounds__(128, 4) void attn_mma() {
    extern __shared__ char asm_[];
    const uint32_t sbase = smem_u32(asm_);
    const int tid = threadIdx.x;
    const int wid = tid >> 5, lane = tid & 31;
    const int g = lane >> 2, tig = lane & 3;
    const int wq = wid * 16;
    const int qt = (int)gridDim.x - 1 - (int)blockIdx.x;  // heavy first
    const int h  = blockIdx.y;
    const int q0 = qt * 64;
    const int nkv = qt + 1;

    const uint32_t aRow = lane & 15;
    const uint32_t aSel = ((lane >> 4) & 1) * 16;
    const uint32_t bRow = (lane & 7) + ((lane & 16) ? 8 : 0);
    const uint32_t bSel = (lane & 8) ? 16 : 0;
    const int vrow = lane & 7;
    const int vmk  = (lane >> 3) & 1;
    const int vmn  = (lane >> 4) & 1;

    // ones B-fragment for the l column: n-group lane g==0 holds B[k][0]=1
    const uint32_t ones = (g == 0) ? 0x3C003C00u : 0u;

    auto fetch_kv = [&](int blk, int b) {
        const uint32_t st = sbase + (uint32_t)(AKV_B + b * AST_B);
        #pragma unroll
        for (int i = 0; i < 8; i++) {
            int idx = tid + i * 128;
            int isV = idx >> 9;
            int r = (idx & 511) >> 3, cc = idx & 7;
            const __half* src = (isV ? g_V : g_K) + (size_t)(blk * 64 + r) * 64 + cc * 8;
            cp_async16(st + (isV ? AV_B : 0) + r * AROW + cc * 16, src);
        }
        CP_COMMIT();
    };

    fetch_kv(0, 0);
    {
        #pragma unroll
        for (int i = 0; i < 4; i++) {
            int idx = tid + i * 128;
            int r = idx >> 3, cc = idx & 7;
            cp_async16(sbase + (uint32_t)(AQ_B + r * AROW + cc * 16),
                       &g_Q[(size_t)(q0 + r) * 1024 + h * 64 + cc * 8]);
        }
        CP_COMMIT();
    }
    CP_WAIT(0);
    __syncthreads();

    uint32_t qa[4][4];
    #pragma unroll
    for (int ks = 0; ks < 4; ks++) {
        uint32_t ra = sbase + (uint32_t)(AQ_B + (wq + aRow) * AROW + ks * 32) + aSel;
        ldsm_x4(qa[ks][0], qa[ks][1], qa[ks][2], qa[ks][3], ra);
    }

    float o[8][4], ol[4];
    #pragma unroll
    for (int nt = 0; nt < 8; nt++)
        #pragma unroll
        for (int j = 0; j < 4; j++) o[nt][j] = 0.f;
    ol[0] = ol[1] = ol[2] = ol[3] = 0.f;
    float m0r = -1e30f, m1r = -1e30f;

    for (int kb = 0; kb < nkv; kb++) {
        const int buf = kb & 1;
        if (kb > 0) {
            CP_WAIT(0);
            __syncthreads();
        }
        if (kb + 1 < nkv) fetch_kv(kb + 1, buf ^ 1);

        const uint32_t stb = sbase + (uint32_t)(AKV_B + buf * AST_B);
        const int s0 = kb * 64;

        // S = Q @ K^T  (log2-domain logits)
        float s[8][4];
        #pragma unroll
        for (int nt = 0; nt < 8; nt++)
            s[nt][0] = s[nt][1] = s[nt][2] = s[nt][3] = 0.f;
        #pragma unroll
        for (int ntp = 0; ntp < 4; ntp++) {
            #pragma unroll
            for (int ks = 0; ks < 4; ks++) {
                uint32_t addr = stb + (uint32_t)((ntp * 16 + bRow) * AROW + ks * 32) + bSel;
                uint32_t k0, k1, k2, k3;
                ldsm_x4(k0, k1, k2, k3, addr);
                mma_f16(s[2 * ntp],     qa[ks], k0, k1);
                mma_f16(s[2 * ntp + 1], qa[ks], k2, k3);
            }
        }

        if (kb == qt) {
            int row0 = q0 + wq + g, row1 = row0 + 8;
            #pragma unroll
            for (int nt = 0; nt < 8; nt++) {
                int c0 = s0 + nt * 8 + 2 * tig;
                if (c0     > row0) s[nt][0] = -1e30f;
                if (c0 + 1 > row0) s[nt][1] = -1e30f;
                if (c0     > row1) s[nt][2] = -1e30f;
                if (c0 + 1 > row1) s[nt][3] = -1e30f;
            }
        }

        // max reduce (log2 domain)
        float rm0 = -1e30f, rm1 = -1e30f;
        #pragma unroll
        for (int nt = 0; nt < 8; nt++) {
            rm0 = fmaxf(rm0, fmaxf(s[nt][0], s[nt][1]));
            rm1 = fmaxf(rm1, fmaxf(s[nt][2], s[nt][3]));
        }
        rm0 = fmaxf(rm0, __shfl_xor_sync(0xffffffffu, rm0, 1));
        rm0 = fmaxf(rm0, __shfl_xor_sync(0xffffffffu, rm0, 2));
        rm1 = fmaxf(rm1, __shfl_xor_sync(0xffffffffu, rm1, 1));
        rm1 = fmaxf(rm1, __shfl_xor_sync(0xffffffffu, rm1, 2));
        float mn0 = fmaxf(m0r, rm0), mn1 = fmaxf(m1r, rm1);
        float al0 = ex2_f32(m0r - mn0), al1 = ex2_f32(m1r - mn1);
        m0r = mn0; m1r = mn1;

        // O *= alpha (skip when max unchanged: alpha == 1 exactly)
        if (al0 < 1.f || al1 < 1.f) {
            #pragma unroll
            for (int nt = 0; nt < 8; nt++) {
                o[nt][0] *= al0; o[nt][1] *= al0;
                o[nt][2] *= al1; o[nt][3] *= al1;
            }
            ol[0] *= al0; ol[1] *= al0; ol[2] *= al1; ol[3] *= al1;
        }

        // P via fp16 ex2; PV (+ ones column accumulates l)
        #pragma unroll
        for (int ks = 0; ks < 4; ks++) {
            uint32_t pa[4];
            pa[0] = ex2_h2(packh(s[2 * ks][0]     - mn0, s[2 * ks][1]     - mn0));
            pa[1] = ex2_h2(packh(s[2 * ks][2]     - mn1, s[2 * ks][3]     - mn1));
            pa[2] = ex2_h2(packh(s[2 * ks + 1][0] - mn0, s[2 * ks + 1][1] - mn0));
            pa[3] = ex2_h2(packh(s[2 * ks + 1][2] - mn1, s[2 * ks + 1][3] - mn1));
            #pragma unroll
            for (int ntp = 0; ntp < 4; ntp++) {
                uint32_t rowk = ks * 16 + vmk * 8 + vrow;
                uint32_t coln = ntp * 16 + vmn * 8;
                uint32_t va = stb + AV_B + rowk * AROW + coln * 2;
                uint32_t v0, v1, v2, v3;
                ldsm_x4_t(v0, v1, v2, v3, va);
                mma_f16(o[2 * ntp],     pa, v0, v1);
                mma_f16(o[2 * ntp + 1], pa, v2, v3);
            }
            mma_f16(ol, pa, ones, ones);   // l += P @ 1
        }
    }

    // l lives in lanes tig==0; broadcast within quad
    float l0r = __shfl_sync(0xffffffffu, ol[0], lane & 28);
    float l1r = __shfl_sync(0xffffffffu, ol[2], lane & 28);

    // normalize + write ctx as fp16 hi/lo (feeds GEMM2 2-term)
    float inv0 = 1.0f / l0r, inv1 = 1.0f / l1r;
    int row0 = q0 + wq + g;
    #pragma unroll
    for (int nt = 0; nt < 8; nt++) {
        int col = h * 64 + nt * 8 + 2 * tig;
        float v0 = o[nt][0] * inv0, v1 = o[nt][1] * inv0;
        float v2 = o[nt][2] * inv1, v3 = o[nt][3] * inv1;
        __half h0, l0, h1, l1;
        hsplit(v0, h0, l0); hsplit(v1, h1, l1);
        *(__half2*)&g_Ch[(size_t)row0 * E_DIM + col] = __half2{h0, h1};
        *(__half2*)&g_Cl[(size_t)row0 * E_DIM + col] = __half2{l0, l1};
        hsplit(v2, h0, l0); hsplit(v3, h1, l1);
        *(__half2*)&g_Ch[(size_t)(row0 + 8) * E_DIM + col] = __half2{h0, h1};
        *(__half2*)&g_Cl[(size_t)(row0 + 8) * E_DIM + col] = __half2{l0, l1};
    }
}

// ---------------- launch ----------------
extern "C" void kernel_launch(void* const* d_in, const int* in_sizes, int n_in,
                              void* d_out, int out_size) {
    const float* hidden = (const float*)d_in[0];
    const float* Wq     = (const float*)d_in[1];
    const float* Wk     = (const float*)d_in[2];
    const float* Wv     = (const float*)d_in[3];
    const float* q2l    = (const float*)d_in[4];
    const float* vup    = (const float*)d_in[5];
    const float* Wout   = (const float*)d_in[6];
    float* out = (float*)d_out;

    void *w1h, *w2h, *xh, *xl, *ch, *cl;
    cudaGetSymbolAddress(&w1h, g_W1h);
    cudaGetSymbolAddress(&w2h, g_W2h);
    cudaGetSymbolAddress(&xh,  g_Xh);   cudaGetSymbolAddress(&xl,  g_Xl);
    cudaGetSymbolAddress(&ch,  g_Ch);   cudaGetSymbolAddress(&cl,  g_Cl);

    cudaFuncSetAttribute(gemm_2t,  cudaFuncAttributeMaxDynamicSharedMemorySize, GEMM_SMEM);
    cudaFuncSetAttribute(attn_mma, cudaFuncAttributeMaxDynamicSharedMemorySize, ATTN_SMEM);

    prep_w1_kernel<<<dim3(16, 16), 256>>>(Wq, q2l);
    prep_kv_kernel<<<256, 256>>>(Wk, Wv);
    prep_w2_kernel<<<dim3(16, 16), 256>>>(vup, Wout);

    split_kernel<<<T_SEQ * E_DIM / 1024, 256>>>(hidden, (__half*)xh, (__half*)xl);

    // GEMM1 (fp16 2-term): emits fp16 Q (log2-scaled) / K / V
    gemm_2t<<<dim3(NMID / 64, T_SEQ / 128), 256, GEMM_SMEM>>>(
        (const __half*)xh, (const __half*)xl, (const __half*)w1h,
        out /*unused*/, NMID, E_DIM, 1);

    // attention: 64-row q tiles, log2 softmax, l via ones-column
    attn_mma<<<dim3(T_SEQ / 64, H_NUM), 128, ATTN_SMEM>>>();

    // GEMM2 (fp16 2-term): out = (Ch + Cl) @ W2h^T
    gemm_2t<<<dim3(E_DIM / 64, T_SEQ / 128), 256, GEMM_SMEM>>>(
        (const __half*)ch, (const __half*)cl, (const __half*)w2h,
        out, E_DIM, E_DIM, 0);
}